// round 11
// baseline (speedup 1.0000x reference)
#include <cuda_runtime.h>
#include <cuda_fp16.h>
#include <math.h>

#define N_NODES 20000
#define N_EDGES 320000
#define NPB 8
#define PW 4      // warps (nodes) per prop block

// ---------------- device scratch ----------------
__device__ float  g_xA[N_NODES*13*32];
__device__ float  g_xB[N_NODES*13*32];
__device__ __half g_h [N_NODES*12*32];
__device__ __half g_pA[N_NODES*12*32];
__device__ __half g_pB[N_NODES*12*32];
__device__ float  g_s [N_NODES*12*32];
__device__ float  g_hl[8*N_NODES*32];
__device__ int    g_rowptr[N_NODES+1];
__device__ int    g_curs[N_NODES];
__device__ int    g_cnt[N_NODES];
__device__ float  g_invdeg[N_NODES];
__device__ int    g_col[N_EDGES];
__device__ double g_statsS[32*64];
__device__ float  g_affine[64];
__device__ int    g_done;

__device__ __forceinline__ __half2 H2(unsigned int u){ return *reinterpret_cast<__half2*>(&u); }
__device__ __forceinline__ unsigned int U2(__half2 h){ return *reinterpret_cast<unsigned int*>(&h); }

// ---------------- packed f32x2 helpers ----------------
union Pun4 { float4 f; ulonglong2 u; };

__device__ __forceinline__ unsigned long long ffma2(unsigned long long a, unsigned long long b, unsigned long long c){
    unsigned long long d;
    asm("fma.rn.f32x2 %0, %1, %2, %3;" : "=l"(d) : "l"(a), "l"(b), "l"(c));
    return d;
}
__device__ __forceinline__ unsigned long long packf2(float lo, float hi){
    unsigned long long d;
    asm("mov.b64 %0, {%1, %2};" : "=l"(d) : "f"(lo), "f"(hi));
    return d;
}
__device__ __forceinline__ float2 unpackf2(unsigned long long v){
    float2 r;
    asm("mov.b64 {%0, %1}, %2;" : "=f"(r.x), "=f"(r.y) : "l"(v));
    return r;
}

// ---------------- setup ----------------
__global__ void k_hist(const int* __restrict__ dst){
    int i = blockIdx.x*256 + threadIdx.x;
    if(i < 64) g_affine[i] = (i < 32) ? 1.f : 0.f;
    if(i < N_EDGES) atomicAdd(&g_cnt[dst[i]], 1);
}

__global__ void k_scan(){
    const int CH = 20;
    int tid = threadIdx.x;
    int b0 = tid*CH; if(b0 > N_NODES) b0 = N_NODES;
    int b1 = b0 + CH; if(b1 > N_NODES) b1 = N_NODES;
    int sum = 0;
    for(int i = b0; i < b1; i++) sum += g_cnt[i];
    int lane = tid & 31, w = tid >> 5;
    int v = sum;
#pragma unroll
    for(int o = 1; o < 32; o <<= 1){
        int t = __shfl_up_sync(0xffffffffu, v, o);
        if(lane >= o) v += t;
    }
    __shared__ int wsum[32];
    if(lane == 31) wsum[w] = v;
    __syncthreads();
    if(w == 0){
        int x = wsum[lane];
#pragma unroll
        for(int o = 1; o < 32; o <<= 1){
            int t = __shfl_up_sync(0xffffffffu, x, o);
            if(lane >= o) x += t;
        }
        wsum[lane] = x;
    }
    __syncthreads();
    int pre = v - sum + ((w > 0) ? wsum[w-1] : 0);
    int run = pre;
    for(int i = b0; i < b1; i++){
        int c = g_cnt[i];
        g_curs[i] = run;
        run += c;
        g_rowptr[i+1] = run;
        g_invdeg[i] = 1.f/(float)(c > 0 ? c : 1);
        g_cnt[i] = 0;
    }
    if(tid == 0) g_rowptr[0] = 0;
}

// ---------------- conv body (flat 256 threads; 8 nodes): gated conv -> h(fp16), hl ----------------
template<int TIN, int D, bool ENTER, bool LAST>
__device__ __forceinline__ void conv_body(
    int n0, float* sm,
    const float* __restrict__ xin,
    const float* __restrict__ ew, const float* __restrict__ eb,
    const float* __restrict__ fw_g, const float* __restrict__ fb_g,
    const float* __restrict__ gw_g, const float* __restrict__ gb_g,
    float* __restrict__ hl_out, float* __restrict__ xsave)
{
    constexpr int TOUT = TIN - D;
    constexpr int NP2  = TOUT/2;
    constexpr int ODD  = TOUT & 1;
    constexpr int NQ   = (TIN + 3)/4;
    constexpr int TP   = 20;
    float* wq  = sm;
    float* ews = sm + 4096;
    float* xs  = ews + (ENTER ? 128 : 0);

    int tid = threadIdx.x;
    int tx = tid & 31, ty = tid >> 5;
    for(int j = tid; j < 1024; j += 256){
        int o = j & 31, i = j >> 5;
        float4 v;
        v.x = fw_g[(o*32+i)*2+0];
        v.y = fw_g[(o*32+i)*2+1];
        v.z = gw_g[(o*32+i)*2+0];
        v.w = gw_g[(o*32+i)*2+1];
        ((float4*)wq)[j] = v;
    }
    if(ENTER){
        if(tid < 96) ews[tid] = ew[tid];
        if(tid < 32) ews[96+tid] = eb[tid];
    }
    __syncthreads();

    int n = n0 + ty;
    float* xrow = xs + ty*(32*TP);
    if(ENTER){
        const float* ip = xin + n*(TIN*3);
        float we0 = ews[tx*3+0], we1 = ews[tx*3+1], we2 = ews[tx*3+2], be = ews[96+tx];
#pragma unroll
        for(int tt = 0; tt < TIN; tt++){
            float v = be + we0*ip[tt*3+0] + we1*ip[tt*3+1] + we2*ip[tt*3+2];
            xrow[tx*TP+tt] = v;
            xsave[(n*TIN+tt)*32+tx] = v;
        }
    } else {
        float scl = g_affine[tx], bia = g_affine[32+tx];
        const float* xp = xin + n*(TIN*32);
#pragma unroll
        for(int tt = 0; tt < TIN; tt++)
            xrow[tx*TP+tt] = xp[tt*32+tx]*scl + bia;
    }
    __syncwarp();

    float fb = fb_g[tx], gb = gb_g[tx];
    unsigned long long f2[NP2 ? NP2 : 1], g2[NP2 ? NP2 : 1];
    {
        unsigned long long fbp = packf2(fb, fb), gbp = packf2(gb, gb);
#pragma unroll
        for(int j = 0; j < NP2; j++){ f2[j] = fbp; g2[j] = gbp; }
    }
    float fod = fb, god = gb;

#pragma unroll
    for(int i = 0; i < 32; i++){
        float4 w4 = ((const float4*)wq)[i*32+tx];
        unsigned long long W0f = packf2(w4.x, w4.x), W1f = packf2(w4.y, w4.y);
        unsigned long long W0g = packf2(w4.z, w4.z), W1g = packf2(w4.w, w4.w);
        Pun4 t4[NQ];
        const float4* xq = (const float4*)(xrow + i*TP);
#pragma unroll
        for(int q = 0; q < NQ; q++) t4[q].f = xq[q];
        float xv[NQ*4];
#pragma unroll
        for(int q = 0; q < NQ; q++){
            xv[q*4+0] = t4[q].f.x; xv[q*4+1] = t4[q].f.y;
            xv[q*4+2] = t4[q].f.z; xv[q*4+3] = t4[q].f.w;
        }
#pragma unroll
        for(int j = 0; j < NP2; j++){
            unsigned long long Aj = (j & 1) ? t4[j>>1].u.y : t4[j>>1].u.x;
            f2[j] = ffma2(Aj, W0f, f2[j]);
            g2[j] = ffma2(Aj, W0g, g2[j]);
            if(D & 1){
                unsigned long long Sj = packf2(xv[2*j+1], xv[2*j+2]);
                f2[j] = ffma2(Sj, W1f, f2[j]);
                g2[j] = ffma2(Sj, W1g, g2[j]);
            } else {
                int j1 = j + D/2;
                unsigned long long Aj1 = (j1 & 1) ? t4[j1>>1].u.y : t4[j1>>1].u.x;
                f2[j] = ffma2(Aj1, W1f, f2[j]);
                g2[j] = ffma2(Aj1, W1g, g2[j]);
            }
        }
        if(ODD){
            float x0 = xv[TOUT-1], x1 = xv[TOUT-1+D];
            fod += w4.x*x0 + w4.y*x1;
            god += w4.z*x0 + w4.w*x1;
        }
    }

    if(!LAST){
        float hlast = 0.f;
#pragma unroll
        for(int j = 0; j < NP2; j++){
            float2 ff = unpackf2(f2[j]);
            float2 gg = unpackf2(g2[j]);
            float h0 = tanhf(ff.x) * (1.f/(1.f + expf(-gg.x)));
            float h1 = tanhf(ff.y) * (1.f/(1.f + expf(-gg.y)));
            g_h[(n*TOUT + 2*j)*32+tx]   = __float2half_rn(h0);
            g_h[(n*TOUT + 2*j+1)*32+tx] = __float2half_rn(h1);
            if(2*j+1 == TOUT-1) hlast = h1;
        }
        if(ODD){
            float h = tanhf(fod) * (1.f/(1.f + expf(-god)));
            g_h[(n*TOUT + TOUT-1)*32+tx] = __float2half_rn(h);
            hlast = h;
        }
        hl_out[n*32+tx] = hlast;
    } else {
        float h = tanhf(fod) * (1.f/(1.f + expf(-god)));
        hl_out[n*32+tx] = h;
    }
}

template<int TIN, int D, bool ENTER, bool LAST>
__global__ void __launch_bounds__(256) k_conv(
    const float* __restrict__ xin,
    const float* __restrict__ ew, const float* __restrict__ eb,
    const float* __restrict__ fw_g, const float* __restrict__ fb_g,
    const float* __restrict__ gw_g, const float* __restrict__ gb_g,
    float* __restrict__ hl_out, float* __restrict__ xsave)
{
    extern __shared__ float sm[];
    conv_body<TIN,D,ENTER,LAST>(blockIdx.x*NPB, sm, xin, ew, eb,
        fw_g, fb_g, gw_g, gb_g, hl_out, xsave);
}

// fused: blocks [0,1250) do edge fill; rest do conv layer 0
__global__ void __launch_bounds__(256) k_fillconv(
    const int* __restrict__ src, const int* __restrict__ dst,
    const float* __restrict__ xin,
    const float* __restrict__ ew, const float* __restrict__ eb,
    const float* __restrict__ fw_g, const float* __restrict__ fb_g,
    const float* __restrict__ gw_g, const float* __restrict__ gb_g,
    float* __restrict__ hl_out, float* __restrict__ xsave)
{
    extern __shared__ float sm[];
    if(blockIdx.x < 1250){
        int e = blockIdx.x*256 + threadIdx.x;
        if(e < N_EDGES){
            int pos = atomicAdd(&g_curs[dst[e]], 1);
            g_col[pos] = src[e];
        }
    } else {
        conv_body<13,1,true,false>((blockIdx.x-1250)*NPB, sm, xin, ew, eb,
            fw_g, fb_g, gw_g, gb_g, hl_out, xsave);
    }
}

// ---------------- fp16 gather core: one warp per node, contiguous edges ----------------
template<int T>
__device__ __forceinline__ void gather_row_h(const uint4* __restrict__ in,
                                             int n, int lane, float* acc)
{
    constexpr int R  = T*4;
    constexpr int NV = (R + 31)/32;
    constexpr int EG = (NV == 1) ? 8 : 4;
#pragma unroll
    for(int k = 0; k < NV*8; k++) acc[k] = 0.f;
    int beg = g_rowptr[n], end = g_rowptr[n+1];
    int e = beg;
    for(; e + EG <= end; e += EG){
        int s[EG];
#pragma unroll
        for(int j = 0; j < EG; j++) s[j] = g_col[e+j];
        uint4 q[EG*NV];
#pragma unroll
        for(int j = 0; j < EG; j++){
#pragma unroll
            for(int v = 0; v < NV; v++){
                int idx = v*32 + lane;
                if(idx < R) q[j*NV+v] = in[s[j]*R + idx];
            }
        }
#pragma unroll
        for(int v = 0; v < NV; v++){
            int idx = v*32 + lane;
            if(idx < R){
                __half2 tx_[EG], ty_[EG], tz_[EG], tw_[EG];
#pragma unroll
                for(int j = 0; j < EG; j++){
                    tx_[j] = H2(q[j*NV+v].x); ty_[j] = H2(q[j*NV+v].y);
                    tz_[j] = H2(q[j*NV+v].z); tw_[j] = H2(q[j*NV+v].w);
                }
#pragma unroll
                for(int st = 1; st < EG; st <<= 1){
#pragma unroll
                    for(int j = 0; j < EG; j += 2*st){
                        tx_[j] = __hadd2(tx_[j], tx_[j+st]);
                        ty_[j] = __hadd2(ty_[j], ty_[j+st]);
                        tz_[j] = __hadd2(tz_[j], tz_[j+st]);
                        tw_[j] = __hadd2(tw_[j], tw_[j+st]);
                    }
                }
                float2 f;
                f = __half22float2(tx_[0]); acc[v*8+0] += f.x; acc[v*8+1] += f.y;
                f = __half22float2(ty_[0]); acc[v*8+2] += f.x; acc[v*8+3] += f.y;
                f = __half22float2(tz_[0]); acc[v*8+4] += f.x; acc[v*8+5] += f.y;
                f = __half22float2(tw_[0]); acc[v*8+6] += f.x; acc[v*8+7] += f.y;
            }
        }
    }
    for(; e < end; e++){
        int s0 = g_col[e];
        const uint4* r0 = in + s0*R;
#pragma unroll
        for(int v = 0; v < NV; v++){
            int idx = v*32 + lane;
            if(idx < R){
                uint4 q = r0[idx];
                float2 f;
                f = __half22float2(H2(q.x)); acc[v*8+0] += f.x; acc[v*8+1] += f.y;
                f = __half22float2(H2(q.y)); acc[v*8+2] += f.x; acc[v*8+3] += f.y;
                f = __half22float2(H2(q.z)); acc[v*8+4] += f.x; acc[v*8+5] += f.y;
                f = __half22float2(H2(q.w)); acc[v*8+6] += f.x; acc[v*8+7] += f.y;
            }
        }
    }
    float iv = g_invdeg[n];
#pragma unroll
    for(int k = 0; k < NV*8; k++) acc[k] *= iv;
}

// scatter gathered fp32 values into smem tile (t-major, 32 ch)
template<int T>
__device__ __forceinline__ void acc_to_tile(const float* acc, float* tile, int lane){
    constexpr int R  = T*4;
    constexpr int NV = (R + 31)/32;
#pragma unroll
    for(int v = 0; v < NV; v++){
        int idx = v*32 + lane;
        if(idx < R){
            int t = idx >> 2, c0 = (idx & 3) << 3;
            float4* tp = (float4*)(tile + t*32 + c0);
            tp[0] = make_float4(acc[v*8+0], acc[v*8+1], acc[v*8+2], acc[v*8+3]);
            tp[1] = make_float4(acc[v*8+4], acc[v*8+5], acc[v*8+6], acc[v*8+7]);
        }
    }
}

// write fp16-row regs into the fp32 smem tile
template<int T>
__device__ __forceinline__ void regs_to_tile(const uint4* own, float* tile, int lane){
    constexpr int R  = T*4;
    constexpr int NV = (R + 31)/32;
#pragma unroll
    for(int v = 0; v < NV; v++){
        int idx = v*32 + lane;
        if(idx < R){
            uint4 q = own[v];
            int t = idx >> 2, c0 = (idx & 3) << 3;
            float4* tp = (float4*)(tile + t*32 + c0);
            float2 fx = __half22float2(H2(q.x));
            float2 fy = __half22float2(H2(q.y));
            float2 fz = __half22float2(H2(q.z));
            float2 fw = __half22float2(H2(q.w));
            tp[0] = make_float4(fx.x, fx.y, fy.x, fy.y);
            tp[1] = make_float4(fz.x, fz.y, fw.x, fw.y);
        }
    }
}

// packed GEMM: a2[t] += pairs over K of tile[t][c] * W[c][lane]
template<int T>
__device__ __forceinline__ void gemm_acc2(const float* tile, const float* Ws,
                                          int lane, unsigned long long* a2){
#pragma unroll
    for(int c4 = 0; c4 < 8; c4++){
        unsigned long long W01 = packf2(Ws[(c4*4+0)*32+lane], Ws[(c4*4+1)*32+lane]);
        unsigned long long W23 = packf2(Ws[(c4*4+2)*32+lane], Ws[(c4*4+3)*32+lane]);
#pragma unroll
        for(int t = 0; t < T; t++){
            const ulonglong2* rp = (const ulonglong2*)(tile + t*32 + c4*4);
            ulonglong2 sv = *rp;
            a2[t] = ffma2(sv.x, W01, a2[t]);
            a2[t] = ffma2(sv.y, W23, a2[t]);
        }
    }
}

// store gathered acc as fp16 row
template<int T>
__device__ __forceinline__ void acc_store_h(const float* acc, __half* out, int n, int lane){
    constexpr int R  = T*4;
    constexpr int NV = (R + 31)/32;
    uint4* cp = (uint4*)out + n*R;
#pragma unroll
    for(int v = 0; v < NV; v++){
        int idx = v*32 + lane;
        if(idx < R){
            uint4 q;
            q.x = U2(__floats2half2_rn(acc[v*8+0], acc[v*8+1]));
            q.y = U2(__floats2half2_rn(acc[v*8+2], acc[v*8+3]));
            q.z = U2(__floats2half2_rn(acc[v*8+4], acc[v*8+5]));
            q.w = U2(__floats2half2_rn(acc[v*8+6], acc[v*8+7]));
            cp[idx] = q;
        }
    }
}

// ---------------- hop1: p1 = A*h ; s1 = h@W0 + p1@W1 ----------------
template<int T>
__global__ void __launch_bounds__(128) k_hop1(
    const __half* __restrict__ hin, __half* __restrict__ p1out,
    float* __restrict__ s1out, const float* __restrict__ W01g)
{
    constexpr int R  = T*4;
    constexpr int NV = (R + 31)/32;
    __shared__ float Ws[2048];
    __shared__ __align__(16) float smS[PW*12*32];
    int tid = threadIdx.x, lane = tid & 31, wid = tid >> 5;
    for(int j = tid; j < 2048; j += 128) Ws[j] = W01g[j];
    __syncthreads();

    int n = blockIdx.x*PW + wid;
    uint4 own[NV];
    {
        const uint4* r4 = (const uint4*)(hin + n*(T*32));
#pragma unroll
        for(int v = 0; v < NV; v++){
            int idx = v*32 + lane;
            if(idx < R) own[v] = r4[idx];
        }
    }
    float acc[NV*8];
    gather_row_h<T>((const uint4*)hin, n, lane, acc);

    unsigned long long a2[T];
#pragma unroll
    for(int t = 0; t < T; t++) a2[t] = 0ull;
    float* tile = smS + wid*(T*32);

    regs_to_tile<T>(own, tile, lane);   __syncwarp();
    gemm_acc2<T>(tile, Ws, lane, a2);   __syncwarp();   // h@W0
    acc_to_tile<T>(acc, tile, lane);    __syncwarp();
    gemm_acc2<T>(tile, Ws + 1024, lane, a2);            // p1@W1

    acc_store_h<T>(acc, p1out, n, lane);
    float* sp = s1out + n*(T*32) + lane;
#pragma unroll
    for(int t = 0; t < T; t++){
        float2 v = unpackf2(a2[t]);
        sp[t*32] = v.x + v.y;
    }
}

// ---------------- hop2: p2 = A*p1 ; s2 = s1 + p2@W2 (s in place) ----------------
template<int T>
__global__ void __launch_bounds__(128) k_hop2(
    const __half* __restrict__ p1, __half* __restrict__ p2out,
    float* __restrict__ s, const float* __restrict__ W2g)
{
    constexpr int R  = T*4;
    constexpr int NV = (R + 31)/32;
    __shared__ float Ws[1024];
    __shared__ __align__(16) float smS[PW*12*32];
    int tid = threadIdx.x, lane = tid & 31, wid = tid >> 5;
    for(int j = tid; j < 1024; j += 128) Ws[j] = W2g[j];
    __syncthreads();

    int n = blockIdx.x*PW + wid;
    float* sp = s + n*(T*32) + lane;
    float sreg[T];
#pragma unroll
    for(int t = 0; t < T; t++) sreg[t] = sp[t*32];

    float acc[NV*8];
    gather_row_h<T>((const uint4*)p1, n, lane, acc);

    unsigned long long a2[T];
#pragma unroll
    for(int t = 0; t < T; t++) a2[t] = packf2(sreg[t], 0.f);
    float* tile = smS + wid*(T*32);
    acc_to_tile<T>(acc, tile, lane);  __syncwarp();
    gemm_acc2<T>(tile, Ws, lane, a2);

    acc_store_h<T>(acc, p2out, n, lane);
#pragma unroll
    for(int t = 0; t < T; t++){
        float2 v = unpackf2(a2[t]);
        sp[t*32] = v.x + v.y;
    }
}

// ---------------- fin: p3 = A*p2 ; x = s2 + p3@W3 + gcb + affine(xold); BN ----------------
template<int T, int TIN>
__global__ void __launch_bounds__(128) k_fin(
    const __half* __restrict__ p2, const float* __restrict__ s,
    const float* __restrict__ W3g,
    const float* __restrict__ xold, float* __restrict__ xnew,
    const float* __restrict__ gcb,
    const float* __restrict__ bng, const float* __restrict__ bnb, float invCnt)
{
    constexpr int R  = T*4;
    constexpr int NV = (R + 31)/32;
    __shared__ float Ws[1024];
    __shared__ __align__(16) float smS[PW*12*32];
    __shared__ float rs[32*PW], rq[32*PW];
    __shared__ int isLast;
    int tid = threadIdx.x, lane = tid & 31, wid = tid >> 5;
    for(int j = tid; j < 1024; j += 128) Ws[j] = W3g[j];
    __syncthreads();

    int n = blockIdx.x*PW + wid;
    const float* sp = s + n*(T*32) + lane;
    float sreg[T];
#pragma unroll
    for(int t = 0; t < T; t++) sreg[t] = sp[t*32];

    float acc[NV*8];
    gather_row_h<T>((const uint4*)p2, n, lane, acc);

    unsigned long long a2[T];
#pragma unroll
    for(int t = 0; t < T; t++) a2[t] = packf2(sreg[t], 0.f);
    float* tile = smS + wid*(T*32);
    acc_to_tile<T>(acc, tile, lane);  __syncwarp();
    gemm_acc2<T>(tile, Ws, lane, a2);

    float scl = g_affine[lane], bia = g_affine[32+lane];
    float gb  = gcb[lane];
    const float* xo = xold + (n*TIN + (TIN-T))*32 + lane;
    float* xn = xnew + n*(T*32) + lane;
    float sum = 0.f, sq = 0.f;
#pragma unroll
    for(int t = 0; t < T; t++){
        float2 av = unpackf2(a2[t]);
        float v = (av.x + av.y) + gb + xo[t*32]*scl + bia;
        xn[t*32] = v;
        sum += v; sq += v*v;
    }
    rs[tid] = sum; rq[tid] = sq;
    __syncthreads();
    if(tid < 32){
        float ts = 0.f, tq = 0.f;
#pragma unroll
        for(int w = 0; w < PW; w++){ ts += rs[w*32+tid]; tq += rq[w*32+tid]; }
        int sh = (blockIdx.x & 31)*64;
        atomicAdd(&g_statsS[sh+tid],    (double)ts);
        atomicAdd(&g_statsS[sh+32+tid], (double)tq);
    }
    if(tid == 0){
        __threadfence();
        int d = atomicAdd(&g_done, 1);
        isLast = (d == (int)gridDim.x - 1) ? 1 : 0;
    }
    __syncthreads();
    if(isLast){
        __threadfence();
        if(tid < 32){
            double S = 0.0, Q = 0.0;
            for(int k = 0; k < 32; k++){ S += g_statsS[k*64+tid]; Q += g_statsS[k*64+32+tid]; }
            double mu  = S*(double)invCnt;
            double var = Q*(double)invCnt - mu*mu;
            if(var < 0.0) var = 0.0;
            float scale = bng[tid] * rsqrtf((float)var + 1e-5f);
            g_affine[tid]    = scale;
            g_affine[32+tid] = bnb[tid] - (float)mu*scale;
        }
        __syncthreads();
        for(int j = tid; j < 2048; j += 128) g_statsS[j] = 0.0;
        if(tid == 0) g_done = 0;
    }
}

// ---------------- head (f32x2 packed) ----------------
__global__ void __launch_bounds__(256) k_head(
    const float* __restrict__ sw_g, const float* __restrict__ sb_g,
    const float* __restrict__ w1, const float* __restrict__ b1,
    const float* __restrict__ w2, const float* __restrict__ b2,
    float* __restrict__ out)
{
    extern __shared__ float sm[];
    float* hlsT    = sm;
    float* skipacc = sm + 5120;
    float* wbuf    = sm + 9216;
    float* y1s     = sm + 17440;
    int tid = threadIdx.x;
    int n0 = blockIdx.x*16;

    for(int j = tid; j < 8*16*32; j += 256){
        int c = j & 31, m = (j>>5) & 15, l = j>>9;
        hlsT[(l*32+c)*20 + m] = g_hl[l*(N_NODES*32) + (n0+m)*32 + c];
    }
    unsigned long long a2m[8];
    {
        float bs = 0.f;
        for(int l = 0; l < 8; l++) bs += sb_g[l*256+tid];
        unsigned long long bsp = packf2(bs, bs);
#pragma unroll
        for(int j = 0; j < 8; j++) a2m[j] = bsp;
    }
    for(int l = 0; l < 8; l++){
        __syncthreads();
        for(int j = tid; j < 8192; j += 256){
            int c = j & 31, O = j >> 5;
            wbuf[c*257+O] = sw_g[l*8192 + O*32 + c];
        }
        __syncthreads();
#pragma unroll 4
        for(int c = 0; c < 32; c++){
            float w = wbuf[c*257+tid];
            unsigned long long W = packf2(w, w);
            const ulonglong2* hp = (const ulonglong2*)(hlsT + (l*32+c)*20);
#pragma unroll
            for(int m4 = 0; m4 < 4; m4++){
                ulonglong2 h2 = hp[m4];
                a2m[m4*2+0] = ffma2(h2.x, W, a2m[m4*2+0]);
                a2m[m4*2+1] = ffma2(h2.y, W, a2m[m4*2+1]);
            }
        }
    }
    __syncthreads();
#pragma unroll
    for(int j = 0; j < 8; j++){
        float2 v = unpackf2(a2m[j]);
        skipacc[(2*j)*256+tid]   = fmaxf(v.x, 0.f);
        skipacc[(2*j+1)*256+tid] = fmaxf(v.y, 0.f);
    }
    __syncthreads();

    for(int oo = 0; oo < 2; oo++){
        int o = oo*256 + tid;
        unsigned long long acc2[16];
#pragma unroll
        for(int m = 0; m < 16; m++) acc2[m] = 0ull;
        const ulonglong2* wr = (const ulonglong2*)(w1 + o*256);
        const ulonglong2* sa = (const ulonglong2*)skipacc;
        for(int c4 = 0; c4 < 64; c4++){
            ulonglong2 w = wr[c4];
#pragma unroll
            for(int m = 0; m < 16; m++){
                ulonglong2 s = sa[m*64 + c4];
                acc2[m] = ffma2(s.x, w.x, acc2[m]);
                acc2[m] = ffma2(s.y, w.y, acc2[m]);
            }
        }
        float bb = b1[o];
#pragma unroll
        for(int m = 0; m < 16; m++){
            float2 v = unpackf2(acc2[m]);
            y1s[m*512+o] = fmaxf(v.x + v.y + bb, 0.f);
        }
    }
    __syncthreads();

    for(int idx = tid; idx < 16*24; idx += 256){
        int m = idx/24, o = idx - 24*m;
        unsigned long long acc2 = 0ull;
        const ulonglong2* wp = (const ulonglong2*)(w2 + o*512);
        const ulonglong2* yp = (const ulonglong2*)(y1s + m*512);
        for(int c4 = 0; c4 < 128; c4++){
            ulonglong2 ww = wp[c4], yy = yp[c4];
            acc2 = ffma2(ww.x, yy.x, acc2);
            acc2 = ffma2(ww.y, yy.y, acc2);
        }
        float2 v = unpackf2(acc2);
        out[(n0+m)*24 + o] = b2[o] + v.x + v.y;
    }
}

// ---------------- host ----------------
static inline size_t conv_smem(bool enter){
    return (size_t)(4096 + (enter ? 128 : 0) + NPB*32*20) * 4;
}

extern "C" void kernel_launch(void* const* d_in, const int* in_sizes, int n_in,
                              void* d_out, int out_size)
{
    const float* inputs  = (const float*)d_in[0];
    const int*   esrc    = (const int*)  d_in[1];
    const int*   edst    = (const int*)  d_in[2];
    const float* enter_w = (const float*)d_in[3];
    const float* enter_b = (const float*)d_in[4];
    const float* filt_w  = (const float*)d_in[5];
    const float* filt_b  = (const float*)d_in[6];
    const float* gate_w  = (const float*)d_in[7];
    const float* gate_b  = (const float*)d_in[8];
    const float* gc_w    = (const float*)d_in[9];
    const float* gc_b    = (const float*)d_in[10];
    const float* skip_w  = (const float*)d_in[11];
    const float* skip_b  = (const float*)d_in[12];
    const float* bn_g    = (const float*)d_in[13];
    const float* bn_b    = (const float*)d_in[14];
    const float* out1_w  = (const float*)d_in[15];
    const float* out1_b  = (const float*)d_in[16];
    const float* out2_w  = (const float*)d_in[17];
    const float* out2_b  = (const float*)d_in[18];
    float* out = (float*)d_out;

    static int attr_set = 0;
    if(!attr_set){
        cudaFuncSetAttribute(k_head, cudaFuncAttributeMaxDynamicSharedMemorySize, 25632*4);
        attr_set = 1;
    }

    float *xA, *xB, *hl, *ss;
    __half *pA, *pB, *hh;
    cudaGetSymbolAddress((void**)&xA, g_xA);
    cudaGetSymbolAddress((void**)&xB, g_xB);
    cudaGetSymbolAddress((void**)&pA, g_pA);
    cudaGetSymbolAddress((void**)&pB, g_pB);
    cudaGetSymbolAddress((void**)&hh, g_h);
    cudaGetSymbolAddress((void**)&hl, g_hl);
    cudaGetSymbolAddress((void**)&ss, g_s);

    k_hist<<<(N_EDGES+255)/256, 256>>>(edst);
    k_scan<<<1, 1024>>>();

    const int GC = N_NODES/NPB;      // 2500
    const int GP = N_NODES/PW;       // 5000

    // fused: edge fill + conv layer 0 (enter fused)
    k_fillconv<<<1250 + GC, 256, conv_smem(true)>>>(
        esrc, edst,
        inputs, enter_w, enter_b,
        filt_w + 0*2048, filt_b + 0*32, gate_w + 0*2048, gate_b + 0*32,
        hl + 0*N_NODES*32, xA);
    k_hop1<12><<<GP, 128>>>(hh, pA, ss, gc_w + 0*4096);
    k_hop2<12><<<GP, 128>>>(pA, pB, ss, gc_w + 0*4096 + 2048);
    k_fin<12,13><<<GP, 128>>>(pB, ss, gc_w + 0*4096 + 3072, xA, xB,
        gc_b + 0*32, bn_g + 0*32, bn_b + 0*32, 1.f/((float)N_NODES*12.f));

#define LAYER(l, TIN, DD, XIN, XNEW)                                                        \
    {                                                                                       \
        const int t = (TIN) - (DD);                                                         \
        k_conv<TIN, DD, false, false><<<GC, 256, conv_smem(false)>>>(                       \
            XIN, 0, 0,                                                                      \
            filt_w + (l)*2048, filt_b + (l)*32, gate_w + (l)*2048, gate_b + (l)*32,         \
            hl + (l)*N_NODES*32, 0);                                                        \
        k_hop1<(TIN)-(DD)><<<GP, 128>>>(hh, pA, ss, gc_w + (l)*4096);                       \
        k_hop2<(TIN)-(DD)><<<GP, 128>>>(pA, pB, ss, gc_w + (l)*4096 + 2048);                \
        k_fin<(TIN)-(DD), TIN><<<GP, 128>>>(pB, ss, gc_w + (l)*4096 + 3072, XIN, XNEW,      \
            gc_b + (l)*32, bn_g + (l)*32, bn_b + (l)*32, 1.f/((float)N_NODES*(float)t));    \
    }

    LAYER(1, 12, 2, xB, xA)
    LAYER(2, 10, 1, xA, xB)
    LAYER(3,  9, 2, xB, xA)
    LAYER(4,  7, 1, xA, xB)
    LAYER(5,  6, 2, xB, xA)
    LAYER(6,  4, 1, xA, xB)
#undef LAYER

    // layer 7: conv + hl only
    k_conv<3,2,false,true><<<GC, 256, conv_smem(false)>>>(
        xB, 0, 0,
        filt_w + 7*2048, filt_b + 7*32, gate_w + 7*2048, gate_b + 7*32,
        hl + 7*N_NODES*32, 0);

    k_head<<<N_NODES/16, 256, 25632*4>>>(skip_w, skip_b, out1_w, out1_b, out2_w, out2_b, out);
}

// round 12
// speedup vs baseline: 1.0429x; 1.0429x over previous
#include <cuda_runtime.h>
#include <cuda_fp16.h>
#include <math.h>

#define N_NODES 20000
#define N_EDGES 320000
#define NPB 8
#define PW 4      // warps (nodes) per hop block

// ---------------- device scratch ----------------
__device__ float  g_xA[N_NODES*13*32];
__device__ float  g_xB[N_NODES*13*32];
__device__ __half g_h [N_NODES*12*32];
__device__ __half g_pA[N_NODES*12*32];
__device__ __half g_pB[N_NODES*12*32];
__device__ __half g_pC[N_NODES*12*32];
__device__ float  g_hl[8*N_NODES*32];
__device__ int    g_rowptr[N_NODES+1];
__device__ int    g_curs[N_NODES];
__device__ int    g_cnt[N_NODES];
__device__ float  g_invdeg[N_NODES];
__device__ int    g_col[N_EDGES];
__device__ double g_statsS[32*64];
__device__ float  g_affine[64];
__device__ int    g_done;

__device__ __forceinline__ __half2 H2(unsigned int u){ return *reinterpret_cast<__half2*>(&u); }
__device__ __forceinline__ unsigned int U2(__half2 h){ return *reinterpret_cast<unsigned int*>(&h); }

// ---------------- packed f32x2 helpers ----------------
union Pun4 { float4 f; ulonglong2 u; };

__device__ __forceinline__ unsigned long long ffma2(unsigned long long a, unsigned long long b, unsigned long long c){
    unsigned long long d;
    asm("fma.rn.f32x2 %0, %1, %2, %3;" : "=l"(d) : "l"(a), "l"(b), "l"(c));
    return d;
}
__device__ __forceinline__ unsigned long long packf2(float lo, float hi){
    unsigned long long d;
    asm("mov.b64 %0, {%1, %2};" : "=l"(d) : "f"(lo), "f"(hi));
    return d;
}
__device__ __forceinline__ float2 unpackf2(unsigned long long v){
    float2 r;
    asm("mov.b64 {%0, %1}, %2;" : "=f"(r.x), "=f"(r.y) : "l"(v));
    return r;
}

// ---------------- setup ----------------
__global__ void k_hist(const int* __restrict__ dst){
    int i = blockIdx.x*256 + threadIdx.x;
    if(i < 64) g_affine[i] = (i < 32) ? 1.f : 0.f;
    if(i < N_EDGES) atomicAdd(&g_cnt[dst[i]], 1);
}

__global__ void k_scan(){
    const int CH = 20;
    int tid = threadIdx.x;
    int b0 = tid*CH; if(b0 > N_NODES) b0 = N_NODES;
    int b1 = b0 + CH; if(b1 > N_NODES) b1 = N_NODES;
    int sum = 0;
    for(int i = b0; i < b1; i++) sum += g_cnt[i];
    int lane = tid & 31, w = tid >> 5;
    int v = sum;
#pragma unroll
    for(int o = 1; o < 32; o <<= 1){
        int t = __shfl_up_sync(0xffffffffu, v, o);
        if(lane >= o) v += t;
    }
    __shared__ int wsum[32];
    if(lane == 31) wsum[w] = v;
    __syncthreads();
    if(w == 0){
        int x = wsum[lane];
#pragma unroll
        for(int o = 1; o < 32; o <<= 1){
            int t = __shfl_up_sync(0xffffffffu, x, o);
            if(lane >= o) x += t;
        }
        wsum[lane] = x;
    }
    __syncthreads();
    int pre = v - sum + ((w > 0) ? wsum[w-1] : 0);
    int run = pre;
    for(int i = b0; i < b1; i++){
        int c = g_cnt[i];
        g_curs[i] = run;
        run += c;
        g_rowptr[i+1] = run;
        g_invdeg[i] = 1.f/(float)(c > 0 ? c : 1);
        g_cnt[i] = 0;
    }
    if(tid == 0) g_rowptr[0] = 0;
}

// ---------------- conv body (flat 256 threads; 8 nodes): gated conv -> h(fp16), hl ----------------
template<int TIN, int D, bool ENTER, bool LAST>
__device__ __forceinline__ void conv_body(
    int n0, float* sm,
    const float* __restrict__ xin,
    const float* __restrict__ ew, const float* __restrict__ eb,
    const float* __restrict__ fw_g, const float* __restrict__ fb_g,
    const float* __restrict__ gw_g, const float* __restrict__ gb_g,
    float* __restrict__ hl_out, float* __restrict__ xsave)
{
    constexpr int TOUT = TIN - D;
    constexpr int NP2  = TOUT/2;
    constexpr int ODD  = TOUT & 1;
    constexpr int NQ   = (TIN + 3)/4;
    constexpr int TP   = 20;
    float* wq  = sm;
    float* ews = sm + 4096;
    float* xs  = ews + (ENTER ? 128 : 0);

    int tid = threadIdx.x;
    int tx = tid & 31, ty = tid >> 5;
    for(int j = tid; j < 1024; j += 256){
        int o = j & 31, i = j >> 5;
        float4 v;
        v.x = fw_g[(o*32+i)*2+0];
        v.y = fw_g[(o*32+i)*2+1];
        v.z = gw_g[(o*32+i)*2+0];
        v.w = gw_g[(o*32+i)*2+1];
        ((float4*)wq)[j] = v;
    }
    if(ENTER){
        if(tid < 96) ews[tid] = ew[tid];
        if(tid < 32) ews[96+tid] = eb[tid];
    }
    __syncthreads();

    int n = n0 + ty;
    float* xrow = xs + ty*(32*TP);
    if(ENTER){
        const float* ip = xin + n*(TIN*3);
        float we0 = ews[tx*3+0], we1 = ews[tx*3+1], we2 = ews[tx*3+2], be = ews[96+tx];
#pragma unroll
        for(int tt = 0; tt < TIN; tt++){
            float v = be + we0*ip[tt*3+0] + we1*ip[tt*3+1] + we2*ip[tt*3+2];
            xrow[tx*TP+tt] = v;
            xsave[(n*TIN+tt)*32+tx] = v;
        }
    } else {
        float scl = g_affine[tx], bia = g_affine[32+tx];
        const float* xp = xin + n*(TIN*32);
#pragma unroll
        for(int tt = 0; tt < TIN; tt++)
            xrow[tx*TP+tt] = xp[tt*32+tx]*scl + bia;
    }
    __syncwarp();

    float fb = fb_g[tx], gb = gb_g[tx];
    unsigned long long f2[NP2 ? NP2 : 1], g2[NP2 ? NP2 : 1];
    {
        unsigned long long fbp = packf2(fb, fb), gbp = packf2(gb, gb);
#pragma unroll
        for(int j = 0; j < NP2; j++){ f2[j] = fbp; g2[j] = gbp; }
    }
    float fod = fb, god = gb;

#pragma unroll
    for(int i = 0; i < 32; i++){
        float4 w4 = ((const float4*)wq)[i*32+tx];
        unsigned long long W0f = packf2(w4.x, w4.x), W1f = packf2(w4.y, w4.y);
        unsigned long long W0g = packf2(w4.z, w4.z), W1g = packf2(w4.w, w4.w);
        Pun4 t4[NQ];
        const float4* xq = (const float4*)(xrow + i*TP);
#pragma unroll
        for(int q = 0; q < NQ; q++) t4[q].f = xq[q];
        float xv[NQ*4];
#pragma unroll
        for(int q = 0; q < NQ; q++){
            xv[q*4+0] = t4[q].f.x; xv[q*4+1] = t4[q].f.y;
            xv[q*4+2] = t4[q].f.z; xv[q*4+3] = t4[q].f.w;
        }
#pragma unroll
        for(int j = 0; j < NP2; j++){
            unsigned long long Aj = (j & 1) ? t4[j>>1].u.y : t4[j>>1].u.x;
            f2[j] = ffma2(Aj, W0f, f2[j]);
            g2[j] = ffma2(Aj, W0g, g2[j]);
            if(D & 1){
                unsigned long long Sj = packf2(xv[2*j+1], xv[2*j+2]);
                f2[j] = ffma2(Sj, W1f, f2[j]);
                g2[j] = ffma2(Sj, W1g, g2[j]);
            } else {
                int j1 = j + D/2;
                unsigned long long Aj1 = (j1 & 1) ? t4[j1>>1].u.y : t4[j1>>1].u.x;
                f2[j] = ffma2(Aj1, W1f, f2[j]);
                g2[j] = ffma2(Aj1, W1g, g2[j]);
            }
        }
        if(ODD){
            float x0 = xv[TOUT-1], x1 = xv[TOUT-1+D];
            fod += w4.x*x0 + w4.y*x1;
            god += w4.z*x0 + w4.w*x1;
        }
    }

    if(!LAST){
        float hlast = 0.f;
#pragma unroll
        for(int j = 0; j < NP2; j++){
            float2 ff = unpackf2(f2[j]);
            float2 gg = unpackf2(g2[j]);
            float h0 = tanhf(ff.x) * (1.f/(1.f + expf(-gg.x)));
            float h1 = tanhf(ff.y) * (1.f/(1.f + expf(-gg.y)));
            g_h[(n*TOUT + 2*j)*32+tx]   = __float2half_rn(h0);
            g_h[(n*TOUT + 2*j+1)*32+tx] = __float2half_rn(h1);
            if(2*j+1 == TOUT-1) hlast = h1;
        }
        if(ODD){
            float h = tanhf(fod) * (1.f/(1.f + expf(-god)));
            g_h[(n*TOUT + TOUT-1)*32+tx] = __float2half_rn(h);
            hlast = h;
        }
        hl_out[n*32+tx] = hlast;
    } else {
        float h = tanhf(fod) * (1.f/(1.f + expf(-god)));
        hl_out[n*32+tx] = h;
    }
}

template<int TIN, int D, bool ENTER, bool LAST>
__global__ void __launch_bounds__(256) k_conv(
    const float* __restrict__ xin,
    const float* __restrict__ ew, const float* __restrict__ eb,
    const float* __restrict__ fw_g, const float* __restrict__ fb_g,
    const float* __restrict__ gw_g, const float* __restrict__ gb_g,
    float* __restrict__ hl_out, float* __restrict__ xsave)
{
    extern __shared__ float sm[];
    conv_body<TIN,D,ENTER,LAST>(blockIdx.x*NPB, sm, xin, ew, eb,
        fw_g, fb_g, gw_g, gb_g, hl_out, xsave);
}

// fused: blocks [0,1250) do edge fill; rest do conv layer 0
__global__ void __launch_bounds__(256) k_fillconv(
    const int* __restrict__ src, const int* __restrict__ dst,
    const float* __restrict__ xin,
    const float* __restrict__ ew, const float* __restrict__ eb,
    const float* __restrict__ fw_g, const float* __restrict__ fb_g,
    const float* __restrict__ gw_g, const float* __restrict__ gb_g,
    float* __restrict__ hl_out, float* __restrict__ xsave)
{
    extern __shared__ float sm[];
    if(blockIdx.x < 1250){
        int e = blockIdx.x*256 + threadIdx.x;
        if(e < N_EDGES){
            int pos = atomicAdd(&g_curs[dst[e]], 1);
            g_col[pos] = src[e];
        }
    } else {
        conv_body<13,1,true,false>((blockIdx.x-1250)*NPB, sm, xin, ew, eb,
            fw_g, fb_g, gw_g, gb_g, hl_out, xsave);
    }
}

// ---------------- fp16 gather core: one warp per node, contiguous edges ----------------
template<int T>
__device__ __forceinline__ void gather_row_h(const uint4* __restrict__ in,
                                             int n, int lane, float* acc)
{
    constexpr int R  = T*4;
    constexpr int NV = (R + 31)/32;
    constexpr int EG = (NV == 1) ? 8 : 4;
#pragma unroll
    for(int k = 0; k < NV*8; k++) acc[k] = 0.f;
    int beg = g_rowptr[n], end = g_rowptr[n+1];
    int e = beg;
    for(; e + EG <= end; e += EG){
        int s[EG];
#pragma unroll
        for(int j = 0; j < EG; j++) s[j] = g_col[e+j];
        uint4 q[EG*NV];
#pragma unroll
        for(int j = 0; j < EG; j++){
#pragma unroll
            for(int v = 0; v < NV; v++){
                int idx = v*32 + lane;
                if(idx < R) q[j*NV+v] = in[s[j]*R + idx];
            }
        }
#pragma unroll
        for(int v = 0; v < NV; v++){
            int idx = v*32 + lane;
            if(idx < R){
                __half2 tx_[EG], ty_[EG], tz_[EG], tw_[EG];
#pragma unroll
                for(int j = 0; j < EG; j++){
                    tx_[j] = H2(q[j*NV+v].x); ty_[j] = H2(q[j*NV+v].y);
                    tz_[j] = H2(q[j*NV+v].z); tw_[j] = H2(q[j*NV+v].w);
                }
#pragma unroll
                for(int st = 1; st < EG; st <<= 1){
#pragma unroll
                    for(int j = 0; j < EG; j += 2*st){
                        tx_[j] = __hadd2(tx_[j], tx_[j+st]);
                        ty_[j] = __hadd2(ty_[j], ty_[j+st]);
                        tz_[j] = __hadd2(tz_[j], tz_[j+st]);
                        tw_[j] = __hadd2(tw_[j], tw_[j+st]);
                    }
                }
                float2 f;
                f = __half22float2(tx_[0]); acc[v*8+0] += f.x; acc[v*8+1] += f.y;
                f = __half22float2(ty_[0]); acc[v*8+2] += f.x; acc[v*8+3] += f.y;
                f = __half22float2(tz_[0]); acc[v*8+4] += f.x; acc[v*8+5] += f.y;
                f = __half22float2(tw_[0]); acc[v*8+6] += f.x; acc[v*8+7] += f.y;
            }
        }
    }
    for(; e < end; e++){
        int s0 = g_col[e];
        const uint4* r0 = in + s0*R;
#pragma unroll
        for(int v = 0; v < NV; v++){
            int idx = v*32 + lane;
            if(idx < R){
                uint4 q = r0[idx];
                float2 f;
                f = __half22float2(H2(q.x)); acc[v*8+0] += f.x; acc[v*8+1] += f.y;
                f = __half22float2(H2(q.y)); acc[v*8+2] += f.x; acc[v*8+3] += f.y;
                f = __half22float2(H2(q.z)); acc[v*8+4] += f.x; acc[v*8+5] += f.y;
                f = __half22float2(H2(q.w)); acc[v*8+6] += f.x; acc[v*8+7] += f.y;
            }
        }
    }
    float iv = g_invdeg[n];
#pragma unroll
    for(int k = 0; k < NV*8; k++) acc[k] *= iv;
}

// load an fp16 row (own node, coalesced) into the fp32 smem tile
template<int T>
__device__ __forceinline__ void row_to_tile(const __half* __restrict__ row,
                                            float* tile, int lane){
    constexpr int R  = T*4;
    constexpr int NV = (R + 31)/32;
    const uint4* r4 = (const uint4*)row;
#pragma unroll
    for(int v = 0; v < NV; v++){
        int idx = v*32 + lane;
        if(idx < R){
            uint4 q = r4[idx];
            int t = idx >> 2, c0 = (idx & 3) << 3;
            float4* tp = (float4*)(tile + t*32 + c0);
            float2 fx = __half22float2(H2(q.x));
            float2 fy = __half22float2(H2(q.y));
            float2 fz = __half22float2(H2(q.z));
            float2 fw = __half22float2(H2(q.w));
            tp[0] = make_float4(fx.x, fx.y, fy.x, fy.y);
            tp[1] = make_float4(fz.x, fz.y, fw.x, fw.y);
        }
    }
}

// packed GEMM: a2[t] += pairs over K of tile[t][c] * W[c][lane]
template<int T>
__device__ __forceinline__ void gemm_acc2(const float* tile, const float* Ws,
                                          int lane, unsigned long long* a2){
#pragma unroll
    for(int c4 = 0; c4 < 8; c4++){
        unsigned long long W01 = packf2(Ws[(c4*4+0)*32+lane], Ws[(c4*4+1)*32+lane]);
        unsigned long long W23 = packf2(Ws[(c4*4+2)*32+lane], Ws[(c4*4+3)*32+lane]);
#pragma unroll
        for(int t = 0; t < T; t++){
            const ulonglong2* rp = (const ulonglong2*)(tile + t*32 + c4*4);
            ulonglong2 sv = *rp;
            a2[t] = ffma2(sv.x, W01, a2[t]);
            a2[t] = ffma2(sv.y, W23, a2[t]);
        }
    }
}

// store gathered acc as fp16 row
template<int T>
__device__ __forceinline__ void acc_store_h(const float* acc, __half* out, int n, int lane){
    constexpr int R  = T*4;
    constexpr int NV = (R + 31)/32;
    uint4* cp = (uint4*)out + n*R;
#pragma unroll
    for(int v = 0; v < NV; v++){
        int idx = v*32 + lane;
        if(idx < R){
            uint4 q;
            q.x = U2(__floats2half2_rn(acc[v*8+0], acc[v*8+1]));
            q.y = U2(__floats2half2_rn(acc[v*8+2], acc[v*8+3]));
            q.z = U2(__floats2half2_rn(acc[v*8+4], acc[v*8+5]));
            q.w = U2(__floats2half2_rn(acc[v*8+6], acc[v*8+7]));
            cp[idx] = q;
        }
    }
}

// ---------------- pure diffusion hop: out = A*in (fp16 -> fp16) ----------------
template<int T>
__global__ void __launch_bounds__(128) k_hop(
    const __half* __restrict__ in, __half* __restrict__ out)
{
    constexpr int NV = (T*4 + 31)/32;
    int tid = threadIdx.x, lane = tid & 31, wid = tid >> 5;
    int n = blockIdx.x*PW + wid;
    float acc[NV*8];
    gather_row_h<T>((const uint4*)in, n, lane, acc);
    acc_store_h<T>(acc, out, n, lane);
}

// ---------------- dense finalize: x = h@W0+p1@W1+p2@W2+p3@W3 + gcb + affine(xold); BN ----------------
template<int T, int TIN>
__global__ void __launch_bounds__(256) k_dense(
    const __half* __restrict__ hrow, const __half* __restrict__ p1,
    const __half* __restrict__ p2,   const __half* __restrict__ p3,
    const float* __restrict__ Wk4,
    const float* __restrict__ xold, float* __restrict__ xnew,
    const float* __restrict__ gcb,
    const float* __restrict__ bng, const float* __restrict__ bnb, float invCnt)
{
    __shared__ float Ws[4096];
    __shared__ __align__(16) float smS[NPB*12*32];
    __shared__ float rs[256], rq[256];
    __shared__ int isLast;
    int tid = threadIdx.x, lane = tid & 31, wid = tid >> 5;
    for(int j = tid; j < 4096; j += 256) Ws[j] = Wk4[j];
    __syncthreads();

    int n = blockIdx.x*NPB + wid;
    unsigned long long a2[T];
#pragma unroll
    for(int t = 0; t < T; t++) a2[t] = 0ull;
    float* tile = smS + wid*(T*32);

    row_to_tile<T>(hrow + n*(T*32), tile, lane);  __syncwarp();
    gemm_acc2<T>(tile, Ws,        lane, a2);      __syncwarp();
    row_to_tile<T>(p1 + n*(T*32), tile, lane);    __syncwarp();
    gemm_acc2<T>(tile, Ws + 1024, lane, a2);      __syncwarp();
    row_to_tile<T>(p2 + n*(T*32), tile, lane);    __syncwarp();
    gemm_acc2<T>(tile, Ws + 2048, lane, a2);      __syncwarp();
    row_to_tile<T>(p3 + n*(T*32), tile, lane);    __syncwarp();
    gemm_acc2<T>(tile, Ws + 3072, lane, a2);

    float scl = g_affine[lane], bia = g_affine[32+lane];
    float gb  = gcb[lane];
    const float* xo = xold + (n*TIN + (TIN-T))*32 + lane;
    float* xn = xnew + n*(T*32) + lane;
    float sum = 0.f, sq = 0.f;
#pragma unroll
    for(int t = 0; t < T; t++){
        float2 av = unpackf2(a2[t]);
        float v = (av.x + av.y) + gb + xo[t*32]*scl + bia;
        xn[t*32] = v;
        sum += v; sq += v*v;
    }
    rs[tid] = sum; rq[tid] = sq;
    __syncthreads();
    if(tid < 32){
        float ts = 0.f, tq = 0.f;
#pragma unroll
        for(int w = 0; w < NPB; w++){ ts += rs[w*32+tid]; tq += rq[w*32+tid]; }
        int sh = (blockIdx.x & 31)*64;
        atomicAdd(&g_statsS[sh+tid],    (double)ts);
        atomicAdd(&g_statsS[sh+32+tid], (double)tq);
    }
    if(tid == 0){
        __threadfence();
        int d = atomicAdd(&g_done, 1);
        isLast = (d == (int)gridDim.x - 1) ? 1 : 0;
    }
    __syncthreads();
    if(isLast){
        __threadfence();
        if(tid < 32){
            double S = 0.0, Q = 0.0;
            for(int k = 0; k < 32; k++){ S += g_statsS[k*64+tid]; Q += g_statsS[k*64+32+tid]; }
            double mu  = S*(double)invCnt;
            double var = Q*(double)invCnt - mu*mu;
            if(var < 0.0) var = 0.0;
            float scale = bng[tid] * rsqrtf((float)var + 1e-5f);
            g_affine[tid]    = scale;
            g_affine[32+tid] = bnb[tid] - (float)mu*scale;
        }
        __syncthreads();
        for(int j = tid; j < 2048; j += 256) g_statsS[j] = 0.0;
        if(tid == 0) g_done = 0;
    }
}

// ---------------- head (f32x2 packed) ----------------
__global__ void __launch_bounds__(256) k_head(
    const float* __restrict__ sw_g, const float* __restrict__ sb_g,
    const float* __restrict__ w1, const float* __restrict__ b1,
    const float* __restrict__ w2, const float* __restrict__ b2,
    float* __restrict__ out)
{
    extern __shared__ float sm[];
    float* hlsT    = sm;
    float* skipacc = sm + 5120;
    float* wbuf    = sm + 9216;
    float* y1s     = sm + 17440;
    int tid = threadIdx.x;
    int n0 = blockIdx.x*16;

    for(int j = tid; j < 8*16*32; j += 256){
        int c = j & 31, m = (j>>5) & 15, l = j>>9;
        hlsT[(l*32+c)*20 + m] = g_hl[l*(N_NODES*32) + (n0+m)*32 + c];
    }
    unsigned long long a2m[8];
    {
        float bs = 0.f;
        for(int l = 0; l < 8; l++) bs += sb_g[l*256+tid];
        unsigned long long bsp = packf2(bs, bs);
#pragma unroll
        for(int j = 0; j < 8; j++) a2m[j] = bsp;
    }
    for(int l = 0; l < 8; l++){
        __syncthreads();
        for(int j = tid; j < 8192; j += 256){
            int c = j & 31, O = j >> 5;
            wbuf[c*257+O] = sw_g[l*8192 + O*32 + c];
        }
        __syncthreads();
#pragma unroll 4
        for(int c = 0; c < 32; c++){
            float w = wbuf[c*257+tid];
            unsigned long long W = packf2(w, w);
            const ulonglong2* hp = (const ulonglong2*)(hlsT + (l*32+c)*20);
#pragma unroll
            for(int m4 = 0; m4 < 4; m4++){
                ulonglong2 h2 = hp[m4];
                a2m[m4*2+0] = ffma2(h2.x, W, a2m[m4*2+0]);
                a2m[m4*2+1] = ffma2(h2.y, W, a2m[m4*2+1]);
            }
        }
    }
    __syncthreads();
#pragma unroll
    for(int j = 0; j < 8; j++){
        float2 v = unpackf2(a2m[j]);
        skipacc[(2*j)*256+tid]   = fmaxf(v.x, 0.f);
        skipacc[(2*j+1)*256+tid] = fmaxf(v.y, 0.f);
    }
    __syncthreads();

    for(int oo = 0; oo < 2; oo++){
        int o = oo*256 + tid;
        unsigned long long acc2[16];
#pragma unroll
        for(int m = 0; m < 16; m++) acc2[m] = 0ull;
        const ulonglong2* wr = (const ulonglong2*)(w1 + o*256);
        const ulonglong2* sa = (const ulonglong2*)skipacc;
        for(int c4 = 0; c4 < 64; c4++){
            ulonglong2 w = wr[c4];
#pragma unroll
            for(int m = 0; m < 16; m++){
                ulonglong2 s = sa[m*64 + c4];
                acc2[m] = ffma2(s.x, w.x, acc2[m]);
                acc2[m] = ffma2(s.y, w.y, acc2[m]);
            }
        }
        float bb = b1[o];
#pragma unroll
        for(int m = 0; m < 16; m++){
            float2 v = unpackf2(acc2[m]);
            y1s[m*512+o] = fmaxf(v.x + v.y + bb, 0.f);
        }
    }
    __syncthreads();

    for(int idx = tid; idx < 16*24; idx += 256){
        int m = idx/24, o = idx - 24*m;
        unsigned long long acc2 = 0ull;
        const ulonglong2* wp = (const ulonglong2*)(w2 + o*512);
        const ulonglong2* yp = (const ulonglong2*)(y1s + m*512);
        for(int c4 = 0; c4 < 128; c4++){
            ulonglong2 ww = wp[c4], yy = yp[c4];
            acc2 = ffma2(ww.x, yy.x, acc2);
            acc2 = ffma2(ww.y, yy.y, acc2);
        }
        float2 v = unpackf2(acc2);
        out[(n0+m)*24 + o] = b2[o] + v.x + v.y;
    }
}

// ---------------- host ----------------
static inline size_t conv_smem(bool enter){
    return (size_t)(4096 + (enter ? 128 : 0) + NPB*32*20) * 4;
}

extern "C" void kernel_launch(void* const* d_in, const int* in_sizes, int n_in,
                              void* d_out, int out_size)
{
    const float* inputs  = (const float*)d_in[0];
    const int*   esrc    = (const int*)  d_in[1];
    const int*   edst    = (const int*)  d_in[2];
    const float* enter_w = (const float*)d_in[3];
    const float* enter_b = (const float*)d_in[4];
    const float* filt_w  = (const float*)d_in[5];
    const float* filt_b  = (const float*)d_in[6];
    const float* gate_w  = (const float*)d_in[7];
    const float* gate_b  = (const float*)d_in[8];
    const float* gc_w    = (const float*)d_in[9];
    const float* gc_b    = (const float*)d_in[10];
    const float* skip_w  = (const float*)d_in[11];
    const float* skip_b  = (const float*)d_in[12];
    const float* bn_g    = (const float*)d_in[13];
    const float* bn_b    = (const float*)d_in[14];
    const float* out1_w  = (const float*)d_in[15];
    const float* out1_b  = (const float*)d_in[16];
    const float* out2_w  = (const float*)d_in[17];
    const float* out2_b  = (const float*)d_in[18];
    float* out = (float*)d_out;

    static int attr_set = 0;
    if(!attr_set){
        cudaFuncSetAttribute(k_head, cudaFuncAttributeMaxDynamicSharedMemorySize, 25632*4);
        attr_set = 1;
    }

    float *xA, *xB, *hl;
    __half *pA, *pB, *pC, *hh;
    cudaGetSymbolAddress((void**)&xA, g_xA);
    cudaGetSymbolAddress((void**)&xB, g_xB);
    cudaGetSymbolAddress((void**)&pA, g_pA);
    cudaGetSymbolAddress((void**)&pB, g_pB);
    cudaGetSymbolAddress((void**)&pC, g_pC);
    cudaGetSymbolAddress((void**)&hh, g_h);
    cudaGetSymbolAddress((void**)&hl, g_hl);

    k_hist<<<(N_EDGES+255)/256, 256>>>(edst);
    k_scan<<<1, 1024>>>();

    const int GC = N_NODES/NPB;      // 2500
    const int GP = N_NODES/PW;       // 5000

    // fused: edge fill + conv layer 0 (enter fused)
    k_fillconv<<<1250 + GC, 256, conv_smem(true)>>>(
        esrc, edst,
        inputs, enter_w, enter_b,
        filt_w + 0*2048, filt_b + 0*32, gate_w + 0*2048, gate_b + 0*32,
        hl + 0*N_NODES*32, xA);
    k_hop<12><<<GP, 128>>>(hh, pA);
    k_hop<12><<<GP, 128>>>(pA, pB);
    k_hop<12><<<GP, 128>>>(pB, pC);
    k_dense<12,13><<<GC, 256>>>(hh, pA, pB, pC, gc_w + 0*4096, xA, xB,
        gc_b + 0*32, bn_g + 0*32, bn_b + 0*32, 1.f/((float)N_NODES*12.f));

#define LAYER(l, TIN, DD, XIN, XNEW)                                                        \
    {                                                                                       \
        const int t = (TIN) - (DD);                                                         \
        k_conv<TIN, DD, false, false><<<GC, 256, conv_smem(false)>>>(                       \
            XIN, 0, 0,                                                                      \
            filt_w + (l)*2048, filt_b + (l)*32, gate_w + (l)*2048, gate_b + (l)*32,         \
            hl + (l)*N_NODES*32, 0);                                                        \
        k_hop<(TIN)-(DD)><<<GP, 128>>>(hh, pA);                                             \
        k_hop<(TIN)-(DD)><<<GP, 128>>>(pA, pB);                                             \
        k_hop<(TIN)-(DD)><<<GP, 128>>>(pB, pC);                                             \
        k_dense<(TIN)-(DD), TIN><<<GC, 256>>>(hh, pA, pB, pC, gc_w + (l)*4096, XIN, XNEW,   \
            gc_b + (l)*32, bn_g + (l)*32, bn_b + (l)*32, 1.f/((float)N_NODES*(float)t));    \
    }

    LAYER(1, 12, 2, xB, xA)
    LAYER(2, 10, 1, xA, xB)
    LAYER(3,  9, 2, xB, xA)
    LAYER(4,  7, 1, xA, xB)
    LAYER(5,  6, 2, xB, xA)
    LAYER(6,  4, 1, xA, xB)
#undef LAYER

    // layer 7: conv + hl only
    k_conv<3,2,false,true><<<GC, 256, conv_smem(false)>>>(
        xB, 0, 0,
        filt_w + 7*2048, filt_b + 7*32, gate_w + 7*2048, gate_b + 7*32,
        hl + 7*N_NODES*32, 0);

    k_head<<<N_NODES/16, 256, 25632*4>>>(skip_w, skip_b, out1_w, out1_b, out2_w, out2_b, out);
}

// round 13
// speedup vs baseline: 1.0680x; 1.0240x over previous
#include <cuda_runtime.h>
#include <cuda_fp16.h>
#include <math.h>

#define N_NODES 20000
#define N_EDGES 320000
#define NPB 8
#define PW 4      // warps (nodes) per prop block

#define GRID_WAIT() asm volatile("griddepcontrol.wait;" ::: "memory")

// ---------------- device scratch ----------------
__device__ float  g_xA[N_NODES*13*32];
__device__ float  g_xB[N_NODES*13*32];
__device__ __half g_h [N_NODES*12*32];
__device__ __half g_pA[N_NODES*12*32];
__device__ __half g_pB[N_NODES*12*32];
__device__ float  g_hl[8*N_NODES*32];
__device__ int    g_rowptr[N_NODES+1];
__device__ int    g_curs[N_NODES];
__device__ int    g_cnt[N_NODES];
__device__ float  g_invdeg[N_NODES];
__device__ int    g_col[N_EDGES];
__device__ double g_statsS[32*64];
__device__ float  g_affine[64];
__device__ int    g_done;

__device__ __forceinline__ __half2 H2(unsigned int u){ return *reinterpret_cast<__half2*>(&u); }
__device__ __forceinline__ unsigned int U2(__half2 h){ return *reinterpret_cast<unsigned int*>(&h); }

// ---------------- packed f32x2 helpers ----------------
union Pun4 { float4 f; ulonglong2 u; };

__device__ __forceinline__ unsigned long long ffma2(unsigned long long a, unsigned long long b, unsigned long long c){
    unsigned long long d;
    asm("fma.rn.f32x2 %0, %1, %2, %3;" : "=l"(d) : "l"(a), "l"(b), "l"(c));
    return d;
}
__device__ __forceinline__ unsigned long long packf2(float lo, float hi){
    unsigned long long d;
    asm("mov.b64 %0, {%1, %2};" : "=l"(d) : "f"(lo), "f"(hi));
    return d;
}
__device__ __forceinline__ float2 unpackf2(unsigned long long v){
    float2 r;
    asm("mov.b64 {%0, %1}, %2;" : "=f"(r.x), "=f"(r.y) : "l"(v));
    return r;
}

// ---------------- setup ----------------
__global__ void k_hist(const int* __restrict__ dst){
    int i = blockIdx.x*256 + threadIdx.x;
    if(i < 64) g_affine[i] = (i < 32) ? 1.f : 0.f;
    if(i < N_EDGES) atomicAdd(&g_cnt[dst[i]], 1);
}

__global__ void k_scan(){
    GRID_WAIT();
    const int CH = 20;
    int tid = threadIdx.x;
    int b0 = tid*CH; if(b0 > N_NODES) b0 = N_NODES;
    int b1 = b0 + CH; if(b1 > N_NODES) b1 = N_NODES;
    int sum = 0;
    for(int i = b0; i < b1; i++) sum += g_cnt[i];
    int lane = tid & 31, w = tid >> 5;
    int v = sum;
#pragma unroll
    for(int o = 1; o < 32; o <<= 1){
        int t = __shfl_up_sync(0xffffffffu, v, o);
        if(lane >= o) v += t;
    }
    __shared__ int wsum[32];
    if(lane == 31) wsum[w] = v;
    __syncthreads();
    if(w == 0){
        int x = wsum[lane];
#pragma unroll
        for(int o = 1; o < 32; o <<= 1){
            int t = __shfl_up_sync(0xffffffffu, x, o);
            if(lane >= o) x += t;
        }
        wsum[lane] = x;
    }
    __syncthreads();
    int pre = v - sum + ((w > 0) ? wsum[w-1] : 0);
    int run = pre;
    for(int i = b0; i < b1; i++){
        int c = g_cnt[i];
        g_curs[i] = run;
        run += c;
        g_rowptr[i+1] = run;
        g_invdeg[i] = 1.f/(float)(c > 0 ? c : 1);
        g_cnt[i] = 0;
    }
    if(tid == 0) g_rowptr[0] = 0;
}

// ---------------- conv body (flat 256 threads; 8 nodes): gated conv -> h(fp16), hl ----------------
template<int TIN, int D, bool ENTER, bool LAST>
__device__ __forceinline__ void conv_body(
    int n0, float* sm,
    const float* __restrict__ xin,
    const float* __restrict__ ew, const float* __restrict__ eb,
    const float* __restrict__ fw_g, const float* __restrict__ fb_g,
    const float* __restrict__ gw_g, const float* __restrict__ gb_g,
    float* __restrict__ hl_out, float* __restrict__ xsave)
{
    constexpr int TOUT = TIN - D;
    constexpr int NP2  = TOUT/2;
    constexpr int ODD  = TOUT & 1;
    constexpr int NQ   = (TIN + 3)/4;
    constexpr int TP   = 20;
    float* wq  = sm;
    float* ews = sm + 4096;
    float* xs  = ews + (ENTER ? 128 : 0);

    int tid = threadIdx.x;
    int tx = tid & 31, ty = tid >> 5;
    for(int j = tid; j < 1024; j += 256){
        int o = j & 31, i = j >> 5;
        float4 v;
        v.x = fw_g[(o*32+i)*2+0];
        v.y = fw_g[(o*32+i)*2+1];
        v.z = gw_g[(o*32+i)*2+0];
        v.w = gw_g[(o*32+i)*2+1];
        ((float4*)wq)[j] = v;
    }
    if(ENTER){
        if(tid < 96) ews[tid] = ew[tid];
        if(tid < 32) ews[96+tid] = eb[tid];
    }
    __syncthreads();
    GRID_WAIT();                       // upstream x / g_affine now visible

    int n = n0 + ty;
    float* xrow = xs + ty*(32*TP);
    if(ENTER){
        const float* ip = xin + n*(TIN*3);
        float we0 = ews[tx*3+0], we1 = ews[tx*3+1], we2 = ews[tx*3+2], be = ews[96+tx];
#pragma unroll
        for(int tt = 0; tt < TIN; tt++){
            float v = be + we0*ip[tt*3+0] + we1*ip[tt*3+1] + we2*ip[tt*3+2];
            xrow[tx*TP+tt] = v;
            xsave[(n*TIN+tt)*32+tx] = v;
        }
    } else {
        float scl = g_affine[tx], bia = g_affine[32+tx];
        const float* xp = xin + n*(TIN*32);
#pragma unroll
        for(int tt = 0; tt < TIN; tt++)
            xrow[tx*TP+tt] = xp[tt*32+tx]*scl + bia;
    }
    __syncwarp();

    float fb = fb_g[tx], gb = gb_g[tx];
    unsigned long long f2[NP2 ? NP2 : 1], g2[NP2 ? NP2 : 1];
    {
        unsigned long long fbp = packf2(fb, fb), gbp = packf2(gb, gb);
#pragma unroll
        for(int j = 0; j < NP2; j++){ f2[j] = fbp; g2[j] = gbp; }
    }
    float fod = fb, god = gb;

#pragma unroll
    for(int i = 0; i < 32; i++){
        float4 w4 = ((const float4*)wq)[i*32+tx];
        unsigned long long W0f = packf2(w4.x, w4.x), W1f = packf2(w4.y, w4.y);
        unsigned long long W0g = packf2(w4.z, w4.z), W1g = packf2(w4.w, w4.w);
        Pun4 t4[NQ];
        const float4* xq = (const float4*)(xrow + i*TP);
#pragma unroll
        for(int q = 0; q < NQ; q++) t4[q].f = xq[q];
        float xv[NQ*4];
#pragma unroll
        for(int q = 0; q < NQ; q++){
            xv[q*4+0] = t4[q].f.x; xv[q*4+1] = t4[q].f.y;
            xv[q*4+2] = t4[q].f.z; xv[q*4+3] = t4[q].f.w;
        }
#pragma unroll
        for(int j = 0; j < NP2; j++){
            unsigned long long Aj = (j & 1) ? t4[j>>1].u.y : t4[j>>1].u.x;
            f2[j] = ffma2(Aj, W0f, f2[j]);
            g2[j] = ffma2(Aj, W0g, g2[j]);
            if(D & 1){
                unsigned long long Sj = packf2(xv[2*j+1], xv[2*j+2]);
                f2[j] = ffma2(Sj, W1f, f2[j]);
                g2[j] = ffma2(Sj, W1g, g2[j]);
            } else {
                int j1 = j + D/2;
                unsigned long long Aj1 = (j1 & 1) ? t4[j1>>1].u.y : t4[j1>>1].u.x;
                f2[j] = ffma2(Aj1, W1f, f2[j]);
                g2[j] = ffma2(Aj1, W1g, g2[j]);
            }
        }
        if(ODD){
            float x0 = xv[TOUT-1], x1 = xv[TOUT-1+D];
            fod += w4.x*x0 + w4.y*x1;
            god += w4.z*x0 + w4.w*x1;
        }
    }

    if(!LAST){
        float hlast = 0.f;
#pragma unroll
        for(int j = 0; j < NP2; j++){
            float2 ff = unpackf2(f2[j]);
            float2 gg = unpackf2(g2[j]);
            float h0 = tanhf(ff.x) * (1.f/(1.f + expf(-gg.x)));
            float h1 = tanhf(ff.y) * (1.f/(1.f + expf(-gg.y)));
            g_h[(n*TOUT + 2*j)*32+tx]   = __float2half_rn(h0);
            g_h[(n*TOUT + 2*j+1)*32+tx] = __float2half_rn(h1);
            if(2*j+1 == TOUT-1) hlast = h1;
        }
        if(ODD){
            float h = tanhf(fod) * (1.f/(1.f + expf(-god)));
            g_h[(n*TOUT + TOUT-1)*32+tx] = __float2half_rn(h);
            hlast = h;
        }
        hl_out[n*32+tx] = hlast;
    } else {
        float h = tanhf(fod) * (1.f/(1.f + expf(-god)));
        hl_out[n*32+tx] = h;
    }
}

template<int TIN, int D, bool ENTER, bool LAST>
__global__ void __launch_bounds__(256) k_conv(
    const float* __restrict__ xin,
    const float* __restrict__ ew, const float* __restrict__ eb,
    const float* __restrict__ fw_g, const float* __restrict__ fb_g,
    const float* __restrict__ gw_g, const float* __restrict__ gb_g,
    float* __restrict__ hl_out, float* __restrict__ xsave)
{
    extern __shared__ float sm[];
    conv_body<TIN,D,ENTER,LAST>(blockIdx.x*NPB, sm, xin, ew, eb,
        fw_g, fb_g, gw_g, gb_g, hl_out, xsave);
}

// fused: blocks [0,1250) do edge fill; rest do conv layer 0
__global__ void __launch_bounds__(256) k_fillconv(
    const int* __restrict__ src, const int* __restrict__ dst,
    const float* __restrict__ xin,
    const float* __restrict__ ew, const float* __restrict__ eb,
    const float* __restrict__ fw_g, const float* __restrict__ fb_g,
    const float* __restrict__ gw_g, const float* __restrict__ gb_g,
    float* __restrict__ hl_out, float* __restrict__ xsave)
{
    extern __shared__ float sm[];
    if(blockIdx.x < 1250){
        GRID_WAIT();
        int e = blockIdx.x*256 + threadIdx.x;
        if(e < N_EDGES){
            int pos = atomicAdd(&g_curs[dst[e]], 1);
            g_col[pos] = src[e];
        }
    } else {
        conv_body<13,1,true,false>((blockIdx.x-1250)*NPB, sm, xin, ew, eb,
            fw_g, fb_g, gw_g, gb_g, hl_out, xsave);
    }
}

// ---------------- fp16 gather core: one warp per node, contiguous edges ----------------
template<int T>
__device__ __forceinline__ void gather_row_h(const uint4* __restrict__ in,
                                             int n, int lane, float* acc)
{
    constexpr int R  = T*4;
    constexpr int NV = (R + 31)/32;
    constexpr int EG = (NV == 1) ? 8 : 4;
#pragma unroll
    for(int k = 0; k < NV*8; k++) acc[k] = 0.f;
    int beg = g_rowptr[n], end = g_rowptr[n+1];
    int e = beg;
    for(; e + EG <= end; e += EG){
        int s[EG];
#pragma unroll
        for(int j = 0; j < EG; j++) s[j] = g_col[e+j];
        uint4 q[EG*NV];
#pragma unroll
        for(int j = 0; j < EG; j++){
#pragma unroll
            for(int v = 0; v < NV; v++){
                int idx = v*32 + lane;
                if(idx < R) q[j*NV+v] = in[s[j]*R + idx];
            }
        }
#pragma unroll
        for(int v = 0; v < NV; v++){
            int idx = v*32 + lane;
            if(idx < R){
                __half2 tx_[EG], ty_[EG], tz_[EG], tw_[EG];
#pragma unroll
                for(int j = 0; j < EG; j++){
                    tx_[j] = H2(q[j*NV+v].x); ty_[j] = H2(q[j*NV+v].y);
                    tz_[j] = H2(q[j*NV+v].z); tw_[j] = H2(q[j*NV+v].w);
                }
#pragma unroll
                for(int st = 1; st < EG; st <<= 1){
#pragma unroll
                    for(int j = 0; j < EG; j += 2*st){
                        tx_[j] = __hadd2(tx_[j], tx_[j+st]);
                        ty_[j] = __hadd2(ty_[j], ty_[j+st]);
                        tz_[j] = __hadd2(tz_[j], tz_[j+st]);
                        tw_[j] = __hadd2(tw_[j], tw_[j+st]);
                    }
                }
                float2 f;
                f = __half22float2(tx_[0]); acc[v*8+0] += f.x; acc[v*8+1] += f.y;
                f = __half22float2(ty_[0]); acc[v*8+2] += f.x; acc[v*8+3] += f.y;
                f = __half22float2(tz_[0]); acc[v*8+4] += f.x; acc[v*8+5] += f.y;
                f = __half22float2(tw_[0]); acc[v*8+6] += f.x; acc[v*8+7] += f.y;
            }
        }
    }
    for(; e < end; e++){
        int s0 = g_col[e];
        const uint4* r0 = in + s0*R;
#pragma unroll
        for(int v = 0; v < NV; v++){
            int idx = v*32 + lane;
            if(idx < R){
                uint4 q = r0[idx];
                float2 f;
                f = __half22float2(H2(q.x)); acc[v*8+0] += f.x; acc[v*8+1] += f.y;
                f = __half22float2(H2(q.y)); acc[v*8+2] += f.x; acc[v*8+3] += f.y;
                f = __half22float2(H2(q.z)); acc[v*8+4] += f.x; acc[v*8+5] += f.y;
                f = __half22float2(H2(q.w)); acc[v*8+6] += f.x; acc[v*8+7] += f.y;
            }
        }
    }
    float iv = g_invdeg[n];
#pragma unroll
    for(int k = 0; k < NV*8; k++) acc[k] *= iv;
}

// scatter gathered fp32 values into smem tile (t-major, 32 ch)
template<int T>
__device__ __forceinline__ void acc_to_tile(const float* acc, float* tile, int lane){
    constexpr int R  = T*4;
    constexpr int NV = (R + 31)/32;
#pragma unroll
    for(int v = 0; v < NV; v++){
        int idx = v*32 + lane;
        if(idx < R){
            int t = idx >> 2, c0 = (idx & 3) << 3;
            float4* tp = (float4*)(tile + t*32 + c0);
            tp[0] = make_float4(acc[v*8+0], acc[v*8+1], acc[v*8+2], acc[v*8+3]);
            tp[1] = make_float4(acc[v*8+4], acc[v*8+5], acc[v*8+6], acc[v*8+7]);
        }
    }
}

// load an fp16 row (own node, coalesced) into the fp32 smem tile
template<int T>
__device__ __forceinline__ void row_to_tile(const __half* __restrict__ row,
                                            float* tile, int lane){
    constexpr int R  = T*4;
    constexpr int NV = (R + 31)/32;
    const uint4* r4 = (const uint4*)row;
#pragma unroll
    for(int v = 0; v < NV; v++){
        int idx = v*32 + lane;
        if(idx < R){
            uint4 q = r4[idx];
            int t = idx >> 2, c0 = (idx & 3) << 3;
            float4* tp = (float4*)(tile + t*32 + c0);
            float2 fx = __half22float2(H2(q.x));
            float2 fy = __half22float2(H2(q.y));
            float2 fz = __half22float2(H2(q.z));
            float2 fw = __half22float2(H2(q.w));
            tp[0] = make_float4(fx.x, fx.y, fy.x, fy.y);
            tp[1] = make_float4(fz.x, fz.y, fw.x, fw.y);
        }
    }
}

// packed GEMM: a2[t] += pairs over K of tile[t][c] * W[c][lane]
template<int T>
__device__ __forceinline__ void gemm_acc2(const float* tile, const float* Ws,
                                          int lane, unsigned long long* a2){
#pragma unroll
    for(int c4 = 0; c4 < 8; c4++){
        unsigned long long W01 = packf2(Ws[(c4*4+0)*32+lane], Ws[(c4*4+1)*32+lane]);
        unsigned long long W23 = packf2(Ws[(c4*4+2)*32+lane], Ws[(c4*4+3)*32+lane]);
#pragma unroll
        for(int t = 0; t < T; t++){
            const ulonglong2* rp = (const ulonglong2*)(tile + t*32 + c4*4);
            ulonglong2 sv = *rp;
            a2[t] = ffma2(sv.x, W01, a2[t]);
            a2[t] = ffma2(sv.y, W23, a2[t]);
        }
    }
}

// store gathered acc as fp16 row
template<int T>
__device__ __forceinline__ void acc_store_h(const float* acc, __half* out, int n, int lane){
    constexpr int R  = T*4;
    constexpr int NV = (R + 31)/32;
    uint4* cp = (uint4*)out + n*R;
#pragma unroll
    for(int v = 0; v < NV; v++){
        int idx = v*32 + lane;
        if(idx < R){
            uint4 q;
            q.x = U2(__floats2half2_rn(acc[v*8+0], acc[v*8+1]));
            q.y = U2(__floats2half2_rn(acc[v*8+2], acc[v*8+3]));
            q.z = U2(__floats2half2_rn(acc[v*8+4], acc[v*8+5]));
            q.w = U2(__floats2half2_rn(acc[v*8+6], acc[v*8+7]));
            cp[idx] = q;
        }
    }
}

// ---------------- pure diffusion hop: out = A*in (fp16 -> fp16) ----------------
template<int T>
__global__ void __launch_bounds__(128) k_hop(
    const __half* __restrict__ in, __half* __restrict__ out)
{
    GRID_WAIT();
    constexpr int NV = (T*4 + 31)/32;
    int tid = threadIdx.x, lane = tid & 31, wid = tid >> 5;
    int n = blockIdx.x*PW + wid;
    float acc[NV*8];
    gather_row_h<T>((const uint4*)in, n, lane, acc);
    acc_store_h<T>(acc, out, n, lane);
}

// ---------------- propfin: p3 = A*p2 ; x = h@W0+p1@W1+p2@W2+p3@W3 + gcb + affine(xold); BN ----------------
template<int T, int TIN>
__global__ void __launch_bounds__(128) k_propfin(
    const __half* __restrict__ in,        // p2
    const __half* __restrict__ p1,
    const float* __restrict__ Wk4,        // 4x 32x32
    const float* __restrict__ xold, float* __restrict__ xnew,
    const float* __restrict__ gcb,
    const float* __restrict__ bng, const float* __restrict__ bnb, float invCnt)
{
    constexpr int NV = (T*4 + 31)/32;
    __shared__ float Ws[4096];
    __shared__ __align__(16) float smS[PW*12*32];
    __shared__ float rs[32*PW], rq[32*PW];
    __shared__ int isLast;
    int tid = threadIdx.x, lane = tid & 31, wid = tid >> 5;
    for(int j = tid; j < 4096; j += 128) Ws[j] = Wk4[j];
    __syncthreads();
    GRID_WAIT();

    int n = blockIdx.x*PW + wid;
    float acc[NV*8];
    gather_row_h<T>((const uint4*)in, n, lane, acc);   // p3

    unsigned long long a2[T];
#pragma unroll
    for(int t = 0; t < T; t++) a2[t] = 0ull;
    float* tile = smS + wid*(T*32);

    row_to_tile<T>(g_h + n*(T*32), tile, lane);  __syncwarp();
    gemm_acc2<T>(tile, Ws,        lane, a2);     __syncwarp();
    row_to_tile<T>(p1 + n*(T*32), tile, lane);   __syncwarp();
    gemm_acc2<T>(tile, Ws + 1024, lane, a2);     __syncwarp();
    row_to_tile<T>(in + n*(T*32), tile, lane);   __syncwarp();
    gemm_acc2<T>(tile, Ws + 2048, lane, a2);     __syncwarp();
    acc_to_tile<T>(acc, tile, lane);             __syncwarp();
    gemm_acc2<T>(tile, Ws + 3072, lane, a2);

    float scl = g_affine[lane], bia = g_affine[32+lane];
    float gb  = gcb[lane];
    const float* xo = xold + (n*TIN + (TIN-T))*32 + lane;
    float* xn = xnew + n*(T*32) + lane;
    float sum = 0.f, sq = 0.f;
#pragma unroll
    for(int t = 0; t < T; t++){
        float2 av = unpackf2(a2[t]);
        float v = (av.x + av.y) + gb + xo[t*32]*scl + bia;
        xn[t*32] = v;
        sum += v; sq += v*v;
    }
    rs[tid] = sum; rq[tid] = sq;
    __syncthreads();
    if(tid < 32){
        float ts = 0.f, tq = 0.f;
#pragma unroll
        for(int w = 0; w < PW; w++){ ts += rs[w*32+tid]; tq += rq[w*32+tid]; }
        int sh = (blockIdx.x & 31)*64;
        atomicAdd(&g_statsS[sh+tid],    (double)ts);
        atomicAdd(&g_statsS[sh+32+tid], (double)tq);
    }
    if(tid == 0){
        __threadfence();
        int d = atomicAdd(&g_done, 1);
        isLast = (d == (int)gridDim.x - 1) ? 1 : 0;
    }
    __syncthreads();
    if(isLast){
        __threadfence();
        if(tid < 32){
            double S = 0.0, Q = 0.0;
            for(int k = 0; k < 32; k++){ S += g_statsS[k*64+tid]; Q += g_statsS[k*64+32+tid]; }
            double mu  = S*(double)invCnt;
            double var = Q*(double)invCnt - mu*mu;
            if(var < 0.0) var = 0.0;
            float scale = bng[tid] * rsqrtf((float)var + 1e-5f);
            g_affine[tid]    = scale;
            g_affine[32+tid] = bnb[tid] - (float)mu*scale;
        }
        __syncthreads();
        for(int j = tid; j < 2048; j += 128) g_statsS[j] = 0.0;
        if(tid == 0) g_done = 0;
    }
}

// ---------------- head (f32x2 packed) ----------------
__global__ void __launch_bounds__(256) k_head(
    const float* __restrict__ sw_g, const float* __restrict__ sb_g,
    const float* __restrict__ w1, const float* __restrict__ b1,
    const float* __restrict__ w2, const float* __restrict__ b2,
    float* __restrict__ out)
{
    GRID_WAIT();
    extern __shared__ float sm[];
    float* hlsT    = sm;
    float* skipacc = sm + 5120;
    float* wbuf    = sm + 9216;
    float* y1s     = sm + 17440;
    int tid = threadIdx.x;
    int n0 = blockIdx.x*16;

    for(int j = tid; j < 8*16*32; j += 256){
        int c = j & 31, m = (j>>5) & 15, l = j>>9;
        hlsT[(l*32+c)*20 + m] = g_hl[l*(N_NODES*32) + (n0+m)*32 + c];
    }
    unsigned long long a2m[8];
    {
        float bs = 0.f;
        for(int l = 0; l < 8; l++) bs += sb_g[l*256+tid];
        unsigned long long bsp = packf2(bs, bs);
#pragma unroll
        for(int j = 0; j < 8; j++) a2m[j] = bsp;
    }
    for(int l = 0; l < 8; l++){
        __syncthreads();
        for(int j = tid; j < 8192; j += 256){
            int c = j & 31, O = j >> 5;
            wbuf[c*257+O] = sw_g[l*8192 + O*32 + c];
        }
        __syncthreads();
#pragma unroll 4
        for(int c = 0; c < 32; c++){
            float w = wbuf[c*257+tid];
            unsigned long long W = packf2(w, w);
            const ulonglong2* hp = (const ulonglong2*)(hlsT + (l*32+c)*20);
#pragma unroll
            for(int m4 = 0; m4 < 4; m4++){
                ulonglong2 h2 = hp[m4];
                a2m[m4*2+0] = ffma2(h2.x, W, a2m[m4*2+0]);
                a2m[m4*2+1] = ffma2(h2.y, W, a2m[m4*2+1]);
            }
        }
    }
    __syncthreads();
#pragma unroll
    for(int j = 0; j < 8; j++){
        float2 v = unpackf2(a2m[j]);
        skipacc[(2*j)*256+tid]   = fmaxf(v.x, 0.f);
        skipacc[(2*j+1)*256+tid] = fmaxf(v.y, 0.f);
    }
    __syncthreads();

    for(int oo = 0; oo < 2; oo++){
        int o = oo*256 + tid;
        unsigned long long acc2[16];
#pragma unroll
        for(int m = 0; m < 16; m++) acc2[m] = 0ull;
        const ulonglong2* wr = (const ulonglong2*)(w1 + o*256);
        const ulonglong2* sa = (const ulonglong2*)skipacc;
        for(int c4 = 0; c4 < 64; c4++){
            ulonglong2 w = wr[c4];
#pragma unroll
            for(int m = 0; m < 16; m++){
                ulonglong2 s = sa[m*64 + c4];
                acc2[m] = ffma2(s.x, w.x, acc2[m]);
                acc2[m] = ffma2(s.y, w.y, acc2[m]);
            }
        }
        float bb = b1[o];
#pragma unroll
        for(int m = 0; m < 16; m++){
            float2 v = unpackf2(acc2[m]);
            y1s[m*512+o] = fmaxf(v.x + v.y + bb, 0.f);
        }
    }
    __syncthreads();

    for(int idx = tid; idx < 16*24; idx += 256){
        int m = idx/24, o = idx - 24*m;
        unsigned long long acc2 = 0ull;
        const ulonglong2* wp = (const ulonglong2*)(w2 + o*512);
        const ulonglong2* yp = (const ulonglong2*)(y1s + m*512);
        for(int c4 = 0; c4 < 128; c4++){
            ulonglong2 ww = wp[c4], yy = yp[c4];
            acc2 = ffma2(ww.x, yy.x, acc2);
            acc2 = ffma2(ww.y, yy.y, acc2);
        }
        float2 v = unpackf2(acc2);
        out[(n0+m)*24 + o] = b2[o] + v.x + v.y;
    }
}

// ---------------- host ----------------
static inline size_t conv_smem(bool enter){
    return (size_t)(4096 + (enter ? 128 : 0) + NPB*32*20) * 4;
}

template<class K, class... A>
static inline void pdl(K k, int grid, int block, size_t smem, A... a){
    cudaLaunchConfig_t cfg;
    memset(&cfg, 0, sizeof(cfg));
    cfg.gridDim  = dim3((unsigned)grid, 1, 1);
    cfg.blockDim = dim3((unsigned)block, 1, 1);
    cfg.dynamicSmemBytes = smem;
    cfg.stream = 0;
    cudaLaunchAttribute at;
    at.id = cudaLaunchAttributeProgrammaticStreamSerialization;
    at.val.programmaticStreamSerializationAllowed = 1;
    cfg.attrs = &at;
    cfg.numAttrs = 1;
    cudaLaunchKernelEx(&cfg, k, a...);
}

extern "C" void kernel_launch(void* const* d_in, const int* in_sizes, int n_in,
                              void* d_out, int out_size)
{
    const float* inputs  = (const float*)d_in[0];
    const int*   esrc    = (const int*)  d_in[1];
    const int*   edst    = (const int*)  d_in[2];
    const float* enter_w = (const float*)d_in[3];
    const float* enter_b = (const float*)d_in[4];
    const float* filt_w  = (const float*)d_in[5];
    const float* filt_b  = (const float*)d_in[6];
    const float* gate_w  = (const float*)d_in[7];
    const float* gate_b  = (const float*)d_in[8];
    const float* gc_w    = (const float*)d_in[9];
    const float* gc_b    = (const float*)d_in[10];
    const float* skip_w  = (const float*)d_in[11];
    const float* skip_b  = (const float*)d_in[12];
    const float* bn_g    = (const float*)d_in[13];
    const float* bn_b    = (const float*)d_in[14];
    const float* out1_w  = (const float*)d_in[15];
    const float* out1_b  = (const float*)d_in[16];
    const float* out2_w  = (const float*)d_in[17];
    const float* out2_b  = (const float*)d_in[18];
    float* out = (float*)d_out;

    static int attr_set = 0;
    if(!attr_set){
        cudaFuncSetAttribute(k_head, cudaFuncAttributeMaxDynamicSharedMemorySize, 25632*4);
        attr_set = 1;
    }

    float *xA, *xB, *hl;
    __half *pA, *pB, *hh;
    cudaGetSymbolAddress((void**)&xA, g_xA);
    cudaGetSymbolAddress((void**)&xB, g_xB);
    cudaGetSymbolAddress((void**)&pA, g_pA);
    cudaGetSymbolAddress((void**)&pB, g_pB);
    cudaGetSymbolAddress((void**)&hh, g_h);
    cudaGetSymbolAddress((void**)&hl, g_hl);

    const int GC = N_NODES/NPB;      // 2500
    const int GP = N_NODES/PW;       // 5000

    k_hist<<<(N_EDGES+255)/256, 256>>>(edst);
    pdl(k_scan, 1, 1024, 0);

    pdl(k_fillconv, 1250 + GC, 256, conv_smem(true),
        esrc, edst, inputs, enter_w, enter_b,
        filt_w + 0*2048, filt_b + 0*32, gate_w + 0*2048, gate_b + 0*32,
        hl + 0*N_NODES*32, xA);
    pdl(k_hop<12>, GP, 128, (size_t)0, (const __half*)hh, pA);
    pdl(k_hop<12>, GP, 128, (size_t)0, (const __half*)pA, pB);
    pdl(k_propfin<12,13>, GP, 128, (size_t)0,
        (const __half*)pB, (const __half*)pA, gc_w + 0*4096,
        (const float*)xA, xB, gc_b + 0*32, bn_g + 0*32, bn_b + 0*32,
        1.f/((float)N_NODES*12.f));

#define LAYER(l, TIN, DD, XIN, XNEW)                                                         \
    {                                                                                        \
        const float t = (float)((TIN) - (DD));                                               \
        pdl(k_conv<TIN, DD, false, false>, GC, 256, conv_smem(false),                        \
            (const float*)XIN, (const float*)0, (const float*)0,                             \
            filt_w + (l)*2048, filt_b + (l)*32, gate_w + (l)*2048, gate_b + (l)*32,          \
            hl + (l)*N_NODES*32, (float*)0);                                                 \
        pdl(k_hop<(TIN)-(DD)>, GP, 128, (size_t)0, (const __half*)hh, pA);                   \
        pdl(k_hop<(TIN)-(DD)>, GP, 128, (size_t)0, (const __half*)pA, pB);                   \
        pdl(k_propfin<(TIN)-(DD), TIN>, GP, 128, (size_t)0,                                  \
            (const __half*)pB, (const __half*)pA, gc_w + (l)*4096,                           \
            (const float*)XIN, XNEW, gc_b + (l)*32, bn_g + (l)*32, bn_b + (l)*32,            \
            1.f/((float)N_NODES*t));                                                         \
    }

    LAYER(1, 12, 2, xB, xA)
    LAYER(2, 10, 1, xA, xB)
    LAYER(3,  9, 2, xB, xA)
    LAYER(4,  7, 1, xA, xB)
    LAYER(5,  6, 2, xB, xA)
    LAYER(6,  4, 1, xA, xB)
#undef LAYER

    // layer 7: conv + hl only
    pdl(k_conv<3,2,false,true>, GC, 256, conv_smem(false),
        (const float*)xB, (const float*)0, (const float*)0,
        filt_w + 7*2048, filt_b + 7*32, gate_w + 7*2048, gate_b + 7*32,
        hl + 7*N_NODES*32, (float*)0);

    pdl(k_head, N_NODES/16, 256, (size_t)(25632*4),
        skip_w, skip_b, out1_w, out1_b, out2_w, out2_b, out);
}

// round 14
// speedup vs baseline: 1.2184x; 1.1408x over previous
#include <cuda_runtime.h>
#include <cuda_fp16.h>
#include <math.h>

#define N_NODES 20000
#define N_EDGES 320000
#define NPB 8
#define PW 4      // warps (nodes) per prop block

#define GRID_WAIT() asm volatile("griddepcontrol.wait;" ::: "memory")

// ---------------- device scratch ----------------
__device__ float  g_xA[N_NODES*13*32];
__device__ float  g_xB[N_NODES*13*32];
__device__ __half g_h [N_NODES*12*32];
__device__ __half g_pA[N_NODES*12*32];
__device__ __half g_pB[N_NODES*12*32];
__device__ float  g_hl[8*N_NODES*32];
__device__ float  g_w1T[256*512];
__device__ float  g_w2T[512*24];
__device__ int    g_rowptr[N_NODES+1];
__device__ int    g_curs[N_NODES];
__device__ int    g_cnt[N_NODES];
__device__ float  g_invdeg[N_NODES];
__device__ int    g_col[N_EDGES];
__device__ double g_statsS[32*64];
__device__ float  g_affine[64];
__device__ int    g_done;

__device__ __forceinline__ __half2 H2(unsigned int u){ return *reinterpret_cast<__half2*>(&u); }
__device__ __forceinline__ unsigned int U2(__half2 h){ return *reinterpret_cast<unsigned int*>(&h); }

// ---------------- packed f32x2 helpers ----------------
union Pun4 { float4 f; ulonglong2 u; };

__device__ __forceinline__ unsigned long long ffma2(unsigned long long a, unsigned long long b, unsigned long long c){
    unsigned long long d;
    asm("fma.rn.f32x2 %0, %1, %2, %3;" : "=l"(d) : "l"(a), "l"(b), "l"(c));
    return d;
}
__device__ __forceinline__ unsigned long long packf2(float lo, float hi){
    unsigned long long d;
    asm("mov.b64 %0, {%1, %2};" : "=l"(d) : "f"(lo), "f"(hi));
    return d;
}
__device__ __forceinline__ float2 unpackf2(unsigned long long v){
    float2 r;
    asm("mov.b64 {%0, %1}, %2;" : "=f"(r.x), "=f"(r.y) : "l"(v));
    return r;
}

// ---------------- setup ----------------
__global__ void k_hist(const int* __restrict__ dst){
    int i = blockIdx.x*256 + threadIdx.x;
    if(i < 64) g_affine[i] = (i < 32) ? 1.f : 0.f;
    if(i < N_EDGES) atomicAdd(&g_cnt[dst[i]], 1);
}

// transpose head weights: w1T[c*512+o] = w1[o*256+c]; w2T[c*24+o] = w2[o*512+c]
__global__ void k_trans(const float* __restrict__ w1, const float* __restrict__ w2){
    int idx = blockIdx.x*256 + threadIdx.x;
    if(idx < 512*256){
        int o = idx >> 8, c = idx & 255;
        g_w1T[c*512 + o] = w1[idx];
    }
    int j = idx - 512*256;
    if(j >= 0 && j < 24*512){
        int o = j >> 9, c = j & 511;
        g_w2T[c*24 + o] = w2[j];
    }
}

__global__ void k_scan(){
    GRID_WAIT();
    const int CH = 20;
    int tid = threadIdx.x;
    int b0 = tid*CH; if(b0 > N_NODES) b0 = N_NODES;
    int b1 = b0 + CH; if(b1 > N_NODES) b1 = N_NODES;
    int sum = 0;
    for(int i = b0; i < b1; i++) sum += g_cnt[i];
    int lane = tid & 31, w = tid >> 5;
    int v = sum;
#pragma unroll
    for(int o = 1; o < 32; o <<= 1){
        int t = __shfl_up_sync(0xffffffffu, v, o);
        if(lane >= o) v += t;
    }
    __shared__ int wsum[32];
    if(lane == 31) wsum[w] = v;
    __syncthreads();
    if(w == 0){
        int x = wsum[lane];
#pragma unroll
        for(int o = 1; o < 32; o <<= 1){
            int t = __shfl_up_sync(0xffffffffu, x, o);
            if(lane >= o) x += t;
        }
        wsum[lane] = x;
    }
    __syncthreads();
    int pre = v - sum + ((w > 0) ? wsum[w-1] : 0);
    int run = pre;
    for(int i = b0; i < b1; i++){
        int c = g_cnt[i];
        g_curs[i] = run;
        run += c;
        g_rowptr[i+1] = run;
        g_invdeg[i] = 1.f/(float)(c > 0 ? c : 1);
        g_cnt[i] = 0;
    }
    if(tid == 0) g_rowptr[0] = 0;
}

// ---------------- conv body (flat 256 threads; 8 nodes): gated conv -> h(fp16), hl ----------------
template<int TIN, int D, bool ENTER, bool LAST>
__device__ __forceinline__ void conv_body(
    int n0, float* sm,
    const float* __restrict__ xin,
    const float* __restrict__ ew, const float* __restrict__ eb,
    const float* __restrict__ fw_g, const float* __restrict__ fb_g,
    const float* __restrict__ gw_g, const float* __restrict__ gb_g,
    float* __restrict__ hl_out, float* __restrict__ xsave)
{
    constexpr int TOUT = TIN - D;
    constexpr int NP2  = TOUT/2;
    constexpr int ODD  = TOUT & 1;
    constexpr int NQ   = (TIN + 3)/4;
    constexpr int TP   = 20;
    float* wq  = sm;
    float* ews = sm + 4096;
    float* xs  = ews + (ENTER ? 128 : 0);

    int tid = threadIdx.x;
    int tx = tid & 31, ty = tid >> 5;
    for(int j = tid; j < 1024; j += 256){
        int o = j & 31, i = j >> 5;
        float4 v;
        v.x = fw_g[(o*32+i)*2+0];
        v.y = fw_g[(o*32+i)*2+1];
        v.z = gw_g[(o*32+i)*2+0];
        v.w = gw_g[(o*32+i)*2+1];
        ((float4*)wq)[j] = v;
    }
    if(ENTER){
        if(tid < 96) ews[tid] = ew[tid];
        if(tid < 32) ews[96+tid] = eb[tid];
    }
    __syncthreads();
    GRID_WAIT();

    int n = n0 + ty;
    float* xrow = xs + ty*(32*TP);
    if(ENTER){
        const float* ip = xin + n*(TIN*3);
        float we0 = ews[tx*3+0], we1 = ews[tx*3+1], we2 = ews[tx*3+2], be = ews[96+tx];
#pragma unroll
        for(int tt = 0; tt < TIN; tt++){
            float v = be + we0*ip[tt*3+0] + we1*ip[tt*3+1] + we2*ip[tt*3+2];
            xrow[tx*TP+tt] = v;
            xsave[(n*TIN+tt)*32+tx] = v;
        }
    } else {
        float scl = g_affine[tx], bia = g_affine[32+tx];
        const float* xp = xin + n*(TIN*32);
#pragma unroll
        for(int tt = 0; tt < TIN; tt++)
            xrow[tx*TP+tt] = xp[tt*32+tx]*scl + bia;
    }
    __syncwarp();

    float fb = fb_g[tx], gb = gb_g[tx];
    unsigned long long f2[NP2 ? NP2 : 1], g2[NP2 ? NP2 : 1];
    {
        unsigned long long fbp = packf2(fb, fb), gbp = packf2(gb, gb);
#pragma unroll
        for(int j = 0; j < NP2; j++){ f2[j] = fbp; g2[j] = gbp; }
    }
    float fod = fb, god = gb;

#pragma unroll
    for(int i = 0; i < 32; i++){
        float4 w4 = ((const float4*)wq)[i*32+tx];
        unsigned long long W0f = packf2(w4.x, w4.x), W1f = packf2(w4.y, w4.y);
        unsigned long long W0g = packf2(w4.z, w4.z), W1g = packf2(w4.w, w4.w);
        Pun4 t4[NQ];
        const float4* xq = (const float4*)(xrow + i*TP);
#pragma unroll
        for(int q = 0; q < NQ; q++) t4[q].f = xq[q];
        float xv[NQ*4];
#pragma unroll
        for(int q = 0; q < NQ; q++){
            xv[q*4+0] = t4[q].f.x; xv[q*4+1] = t4[q].f.y;
            xv[q*4+2] = t4[q].f.z; xv[q*4+3] = t4[q].f.w;
        }
#pragma unroll
        for(int j = 0; j < NP2; j++){
            unsigned long long Aj = (j & 1) ? t4[j>>1].u.y : t4[j>>1].u.x;
            f2[j] = ffma2(Aj, W0f, f2[j]);
            g2[j] = ffma2(Aj, W0g, g2[j]);
            if(D & 1){
                unsigned long long Sj = packf2(xv[2*j+1], xv[2*j+2]);
                f2[j] = ffma2(Sj, W1f, f2[j]);
                g2[j] = ffma2(Sj, W1g, g2[j]);
            } else {
                int j1 = j + D/2;
                unsigned long long Aj1 = (j1 & 1) ? t4[j1>>1].u.y : t4[j1>>1].u.x;
                f2[j] = ffma2(Aj1, W1f, f2[j]);
                g2[j] = ffma2(Aj1, W1g, g2[j]);
            }
        }
        if(ODD){
            float x0 = xv[TOUT-1], x1 = xv[TOUT-1+D];
            fod += w4.x*x0 + w4.y*x1;
            god += w4.z*x0 + w4.w*x1;
        }
    }

    if(!LAST){
        float hlast = 0.f;
#pragma unroll
        for(int j = 0; j < NP2; j++){
            float2 ff = unpackf2(f2[j]);
            float2 gg = unpackf2(g2[j]);
            float h0 = tanhf(ff.x) * (1.f/(1.f + expf(-gg.x)));
            float h1 = tanhf(ff.y) * (1.f/(1.f + expf(-gg.y)));
            g_h[(n*TOUT + 2*j)*32+tx]   = __float2half_rn(h0);
            g_h[(n*TOUT + 2*j+1)*32+tx] = __float2half_rn(h1);
            if(2*j+1 == TOUT-1) hlast = h1;
        }
        if(ODD){
            float h = tanhf(fod) * (1.f/(1.f + expf(-god)));
            g_h[(n*TOUT + TOUT-1)*32+tx] = __float2half_rn(h);
            hlast = h;
        }
        hl_out[n*32+tx] = hlast;
    } else {
        float h = tanhf(fod) * (1.f/(1.f + expf(-god)));
        hl_out[n*32+tx] = h;
    }
}

template<int TIN, int D, bool ENTER, bool LAST>
__global__ void __launch_bounds__(256) k_conv(
    const float* __restrict__ xin,
    const float* __restrict__ ew, const float* __restrict__ eb,
    const float* __restrict__ fw_g, const float* __restrict__ fb_g,
    const float* __restrict__ gw_g, const float* __restrict__ gb_g,
    float* __restrict__ hl_out, float* __restrict__ xsave)
{
    extern __shared__ float sm[];
    conv_body<TIN,D,ENTER,LAST>(blockIdx.x*NPB, sm, xin, ew, eb,
        fw_g, fb_g, gw_g, gb_g, hl_out, xsave);
}

// fused: blocks [0,1250) do edge fill; rest do conv layer 0
__global__ void __launch_bounds__(256) k_fillconv(
    const int* __restrict__ src, const int* __restrict__ dst,
    const float* __restrict__ xin,
    const float* __restrict__ ew, const float* __restrict__ eb,
    const float* __restrict__ fw_g, const float* __restrict__ fb_g,
    const float* __restrict__ gw_g, const float* __restrict__ gb_g,
    float* __restrict__ hl_out, float* __restrict__ xsave)
{
    extern __shared__ float sm[];
    if(blockIdx.x < 1250){
        GRID_WAIT();
        int e = blockIdx.x*256 + threadIdx.x;
        if(e < N_EDGES){
            int pos = atomicAdd(&g_curs[dst[e]], 1);
            g_col[pos] = src[e];
        }
    } else {
        conv_body<13,1,true,false>((blockIdx.x-1250)*NPB, sm, xin, ew, eb,
            fw_g, fb_g, gw_g, gb_g, hl_out, xsave);
    }
}

// ---------------- fp16 gather core: one warp per node, contiguous edges ----------------
template<int T>
__device__ __forceinline__ void gather_row_h(const uint4* __restrict__ in,
                                             int n, int lane, float* acc)
{
    constexpr int R  = T*4;
    constexpr int NV = (R + 31)/32;
    constexpr int EG = (NV == 1) ? 8 : 4;
#pragma unroll
    for(int k = 0; k < NV*8; k++) acc[k] = 0.f;
    int beg = g_rowptr[n], end = g_rowptr[n+1];
    int e = beg;
    for(; e + EG <= end; e += EG){
        int s[EG];
#pragma unroll
        for(int j = 0; j < EG; j++) s[j] = g_col[e+j];
        uint4 q[EG*NV];
#pragma unroll
        for(int j = 0; j < EG; j++){
#pragma unroll
            for(int v = 0; v < NV; v++){
                int idx = v*32 + lane;
                if(idx < R) q[j*NV+v] = in[s[j]*R + idx];
            }
        }
#pragma unroll
        for(int v = 0; v < NV; v++){
            int idx = v*32 + lane;
            if(idx < R){
                __half2 tx_[EG], ty_[EG], tz_[EG], tw_[EG];
#pragma unroll
                for(int j = 0; j < EG; j++){
                    tx_[j] = H2(q[j*NV+v].x); ty_[j] = H2(q[j*NV+v].y);
                    tz_[j] = H2(q[j*NV+v].z); tw_[j] = H2(q[j*NV+v].w);
                }
#pragma unroll
                for(int st = 1; st < EG; st <<= 1){
#pragma unroll
                    for(int j = 0; j < EG; j += 2*st){
                        tx_[j] = __hadd2(tx_[j], tx_[j+st]);
                        ty_[j] = __hadd2(ty_[j], ty_[j+st]);
                        tz_[j] = __hadd2(tz_[j], tz_[j+st]);
                        tw_[j] = __hadd2(tw_[j], tw_[j+st]);
                    }
                }
                float2 f;
                f = __half22float2(tx_[0]); acc[v*8+0] += f.x; acc[v*8+1] += f.y;
                f = __half22float2(ty_[0]); acc[v*8+2] += f.x; acc[v*8+3] += f.y;
                f = __half22float2(tz_[0]); acc[v*8+4] += f.x; acc[v*8+5] += f.y;
                f = __half22float2(tw_[0]); acc[v*8+6] += f.x; acc[v*8+7] += f.y;
            }
        }
    }
    for(; e < end; e++){
        int s0 = g_col[e];
        const uint4* r0 = in + s0*R;
#pragma unroll
        for(int v = 0; v < NV; v++){
            int idx = v*32 + lane;
            if(idx < R){
                uint4 q = r0[idx];
                float2 f;
                f = __half22float2(H2(q.x)); acc[v*8+0] += f.x; acc[v*8+1] += f.y;
                f = __half22float2(H2(q.y)); acc[v*8+2] += f.x; acc[v*8+3] += f.y;
                f = __half22float2(H2(q.z)); acc[v*8+4] += f.x; acc[v*8+5] += f.y;
                f = __half22float2(H2(q.w)); acc[v*8+6] += f.x; acc[v*8+7] += f.y;
            }
        }
    }
    float iv = g_invdeg[n];
#pragma unroll
    for(int k = 0; k < NV*8; k++) acc[k] *= iv;
}

// scatter gathered fp32 values into smem tile (t-major, 32 ch)
template<int T>
__device__ __forceinline__ void acc_to_tile(const float* acc, float* tile, int lane){
    constexpr int R  = T*4;
    constexpr int NV = (R + 31)/32;
#pragma unroll
    for(int v = 0; v < NV; v++){
        int idx = v*32 + lane;
        if(idx < R){
            int t = idx >> 2, c0 = (idx & 3) << 3;
            float4* tp = (float4*)(tile + t*32 + c0);
            tp[0] = make_float4(acc[v*8+0], acc[v*8+1], acc[v*8+2], acc[v*8+3]);
            tp[1] = make_float4(acc[v*8+4], acc[v*8+5], acc[v*8+6], acc[v*8+7]);
        }
    }
}

// load an fp16 row (own node, coalesced) into the fp32 smem tile
template<int T>
__device__ __forceinline__ void row_to_tile(const __half* __restrict__ row,
                                            float* tile, int lane){
    constexpr int R  = T*4;
    constexpr int NV = (R + 31)/32;
    const uint4* r4 = (const uint4*)row;
#pragma unroll
    for(int v = 0; v < NV; v++){
        int idx = v*32 + lane;
        if(idx < R){
            uint4 q = r4[idx];
            int t = idx >> 2, c0 = (idx & 3) << 3;
            float4* tp = (float4*)(tile + t*32 + c0);
            float2 fx = __half22float2(H2(q.x));
            float2 fy = __half22float2(H2(q.y));
            float2 fz = __half22float2(H2(q.z));
            float2 fw = __half22float2(H2(q.w));
            tp[0] = make_float4(fx.x, fx.y, fy.x, fy.y);
            tp[1] = make_float4(fz.x, fz.y, fw.x, fw.y);
        }
    }
}

// packed GEMM: a2[t] += pairs over K of tile[t][c] * W[c][lane]
template<int T>
__device__ __forceinline__ void gemm_acc2(const float* tile, const float* Ws,
                                          int lane, unsigned long long* a2){
#pragma unroll
    for(int c4 = 0; c4 < 8; c4++){
        unsigned long long W01 = packf2(Ws[(c4*4+0)*32+lane], Ws[(c4*4+1)*32+lane]);
        unsigned long long W23 = packf2(Ws[(c4*4+2)*32+lane], Ws[(c4*4+3)*32+lane]);
#pragma unroll
        for(int t = 0; t < T; t++){
            const ulonglong2* rp = (const ulonglong2*)(tile + t*32 + c4*4);
            ulonglong2 sv = *rp;
            a2[t] = ffma2(sv.x, W01, a2[t]);
            a2[t] = ffma2(sv.y, W23, a2[t]);
        }
    }
}

// store gathered acc as fp16 row
template<int T>
__device__ __forceinline__ void acc_store_h(const float* acc, __half* out, int n, int lane){
    constexpr int R  = T*4;
    constexpr int NV = (R + 31)/32;
    uint4* cp = (uint4*)out + n*R;
#pragma unroll
    for(int v = 0; v < NV; v++){
        int idx = v*32 + lane;
        if(idx < R){
            uint4 q;
            q.x = U2(__floats2half2_rn(acc[v*8+0], acc[v*8+1]));
            q.y = U2(__floats2half2_rn(acc[v*8+2], acc[v*8+3]));
            q.z = U2(__floats2half2_rn(acc[v*8+4], acc[v*8+5]));
            q.w = U2(__floats2half2_rn(acc[v*8+6], acc[v*8+7]));
            cp[idx] = q;
        }
    }
}

// ---------------- pure diffusion hop: out = A*in (fp16 -> fp16) ----------------
template<int T>
__global__ void __launch_bounds__(128) k_hop(
    const __half* __restrict__ in, __half* __restrict__ out)
{
    GRID_WAIT();
    constexpr int NV = (T*4 + 31)/32;
    int tid = threadIdx.x, lane = tid & 31, wid = tid >> 5;
    int n = blockIdx.x*PW + wid;
    float acc[NV*8];
    gather_row_h<T>((const uint4*)in, n, lane, acc);
    acc_store_h<T>(acc, out, n, lane);
}

// ---------------- propfin: p3 = A*p2 ; x = h@W0+p1@W1+p2@W2+p3@W3 + gcb + affine(xold); BN ----------------
template<int T, int TIN>
__global__ void __launch_bounds__(128) k_propfin(
    const __half* __restrict__ in,        // p2
    const __half* __restrict__ p1,
    const float* __restrict__ Wk4,        // 4x 32x32
    const float* __restrict__ xold, float* __restrict__ xnew,
    const float* __restrict__ gcb,
    const float* __restrict__ bng, const float* __restrict__ bnb, float invCnt)
{
    constexpr int NV = (T*4 + 31)/32;
    __shared__ float Ws[4096];
    __shared__ __align__(16) float smS[PW*12*32];
    __shared__ float rs[32*PW], rq[32*PW];
    __shared__ int isLast;
    int tid = threadIdx.x, lane = tid & 31, wid = tid >> 5;
    for(int j = tid; j < 4096; j += 128) Ws[j] = Wk4[j];
    __syncthreads();
    GRID_WAIT();

    int n = blockIdx.x*PW + wid;
    float acc[NV*8];
    gather_row_h<T>((const uint4*)in, n, lane, acc);   // p3

    unsigned long long a2[T];
#pragma unroll
    for(int t = 0; t < T; t++) a2[t] = 0ull;
    float* tile = smS + wid*(T*32);

    row_to_tile<T>(g_h + n*(T*32), tile, lane);  __syncwarp();
    gemm_acc2<T>(tile, Ws,        lane, a2);     __syncwarp();
    row_to_tile<T>(p1 + n*(T*32), tile, lane);   __syncwarp();
    gemm_acc2<T>(tile, Ws + 1024, lane, a2);     __syncwarp();
    row_to_tile<T>(in + n*(T*32), tile, lane);   __syncwarp();
    gemm_acc2<T>(tile, Ws + 2048, lane, a2);     __syncwarp();
    acc_to_tile<T>(acc, tile, lane);             __syncwarp();
    gemm_acc2<T>(tile, Ws + 3072, lane, a2);

    float scl = g_affine[lane], bia = g_affine[32+lane];
    float gb  = gcb[lane];
    const float* xo = xold + (n*TIN + (TIN-T))*32 + lane;
    float* xn = xnew + n*(T*32) + lane;
    float sum = 0.f, sq = 0.f;
#pragma unroll
    for(int t = 0; t < T; t++){
        float2 av = unpackf2(a2[t]);
        float v = (av.x + av.y) + gb + xo[t*32]*scl + bia;
        xn[t*32] = v;
        sum += v; sq += v*v;
    }
    rs[tid] = sum; rq[tid] = sq;
    __syncthreads();
    if(tid < 32){
        float ts = 0.f, tq = 0.f;
#pragma unroll
        for(int w = 0; w < PW; w++){ ts += rs[w*32+tid]; tq += rq[w*32+tid]; }
        int sh = (blockIdx.x & 31)*64;
        atomicAdd(&g_statsS[sh+tid],    (double)ts);
        atomicAdd(&g_statsS[sh+32+tid], (double)tq);
    }
    if(tid == 0){
        __threadfence();
        int d = atomicAdd(&g_done, 1);
        isLast = (d == (int)gridDim.x - 1) ? 1 : 0;
    }
    __syncthreads();
    if(isLast){
        __threadfence();
        if(tid < 32){
            double S = 0.0, Q = 0.0;
            for(int k = 0; k < 32; k++){ S += g_statsS[k*64+tid]; Q += g_statsS[k*64+32+tid]; }
            double mu  = S*(double)invCnt;
            double var = Q*(double)invCnt - mu*mu;
            if(var < 0.0) var = 0.0;
            float scale = bng[tid] * rsqrtf((float)var + 1e-5f);
            g_affine[tid]    = scale;
            g_affine[32+tid] = bnb[tid] - (float)mu*scale;
        }
        __syncthreads();
        for(int j = tid; j < 2048; j += 128) g_statsS[j] = 0.0;
        if(tid == 0) g_done = 0;
    }
}

// ---------------- head (f32x2 packed, transposed weights) ----------------
__global__ void __launch_bounds__(256) k_head(
    const float* __restrict__ sw_g, const float* __restrict__ sb_g,
    const float* __restrict__ b1, const float* __restrict__ b2,
    float* __restrict__ out)
{
    GRID_WAIT();
    extern __shared__ float sm[];
    float* hlsT    = sm;
    float* skipacc = sm + 5120;
    float* wbuf    = sm + 9216;
    float* y1s     = sm + 17440;
    int tid = threadIdx.x;
    int n0 = blockIdx.x*16;

    for(int j = tid; j < 8*16*32; j += 256){
        int c = j & 31, m = (j>>5) & 15, l = j>>9;
        hlsT[(l*32+c)*20 + m] = g_hl[l*(N_NODES*32) + (n0+m)*32 + c];
    }
    unsigned long long a2m[8];
    {
        float bs = 0.f;
        for(int l = 0; l < 8; l++) bs += sb_g[l*256+tid];
        unsigned long long bsp = packf2(bs, bs);
#pragma unroll
        for(int j = 0; j < 8; j++) a2m[j] = bsp;
    }
    for(int l = 0; l < 8; l++){
        __syncthreads();
        for(int j = tid; j < 8192; j += 256){
            int c = j & 31, O = j >> 5;
            wbuf[c*257+O] = sw_g[l*8192 + O*32 + c];
        }
        __syncthreads();
#pragma unroll 4
        for(int c = 0; c < 32; c++){
            float w = wbuf[c*257+tid];
            unsigned long long W = packf2(w, w);
            const ulonglong2* hp = (const ulonglong2*)(hlsT + (l*32+c)*20);
#pragma unroll
            for(int m4 = 0; m4 < 4; m4++){
                ulonglong2 h2 = hp[m4];
                a2m[m4*2+0] = ffma2(h2.x, W, a2m[m4*2+0]);
                a2m[m4*2+1] = ffma2(h2.y, W, a2m[m4*2+1]);
            }
        }
    }
    __syncthreads();
#pragma unroll
    for(int j = 0; j < 8; j++){
        float2 v = unpackf2(a2m[j]);
        skipacc[(2*j)*256+tid]   = fmaxf(v.x, 0.f);
        skipacc[(2*j+1)*256+tid] = fmaxf(v.y, 0.f);
    }
    __syncthreads();

    for(int oo = 0; oo < 2; oo++){
        int o = oo*256 + tid;
        unsigned long long acc2[16];
#pragma unroll
        for(int m = 0; m < 16; m++) acc2[m] = 0ull;
        const ulonglong2* sa = (const ulonglong2*)skipacc;
        for(int c4 = 0; c4 < 64; c4++){
            float wa = g_w1T[(c4*4+0)*512 + o];
            float wb = g_w1T[(c4*4+1)*512 + o];
            float wc = g_w1T[(c4*4+2)*512 + o];
            float wd = g_w1T[(c4*4+3)*512 + o];
            unsigned long long Wab = packf2(wa, wb);
            unsigned long long Wcd = packf2(wc, wd);
#pragma unroll
            for(int m = 0; m < 16; m++){
                ulonglong2 s = sa[m*64 + c4];
                acc2[m] = ffma2(s.x, Wab, acc2[m]);
                acc2[m] = ffma2(s.y, Wcd, acc2[m]);
            }
        }
        float bb = b1[o];
#pragma unroll
        for(int m = 0; m < 16; m++){
            float2 v = unpackf2(acc2[m]);
            y1s[m*512+o] = fmaxf(v.x + v.y + bb, 0.f);
        }
    }
    __syncthreads();

    for(int idx = tid; idx < 16*24; idx += 256){
        int m = idx/24, o = idx - 24*m;
        unsigned long long acc2 = 0ull;
        const ulonglong2* yp = (const ulonglong2*)(y1s + m*512);
        for(int c4 = 0; c4 < 128; c4++){
            float wa = g_w2T[(c4*4+0)*24 + o];
            float wb = g_w2T[(c4*4+1)*24 + o];
            float wc = g_w2T[(c4*4+2)*24 + o];
            float wd = g_w2T[(c4*4+3)*24 + o];
            ulonglong2 yy = yp[c4];
            acc2 = ffma2(yy.x, packf2(wa, wb), acc2);
            acc2 = ffma2(yy.y, packf2(wc, wd), acc2);
        }
        float2 v = unpackf2(acc2);
        out[(n0+m)*24 + o] = b2[o] + v.x + v.y;
    }
}

// ---------------- host ----------------
static inline size_t conv_smem(bool enter){
    return (size_t)(4096 + (enter ? 128 : 0) + NPB*32*20) * 4;
}

template<class K, class... A>
static inline void pdl(K k, int grid, int block, size_t smem, A... a){
    cudaLaunchConfig_t cfg;
    memset(&cfg, 0, sizeof(cfg));
    cfg.gridDim  = dim3((unsigned)grid, 1, 1);
    cfg.blockDim = dim3((unsigned)block, 1, 1);
    cfg.dynamicSmemBytes = smem;
    cfg.stream = 0;
    cudaLaunchAttribute at;
    at.id = cudaLaunchAttributeProgrammaticStreamSerialization;
    at.val.programmaticStreamSerializationAllowed = 1;
    cfg.attrs = &at;
    cfg.numAttrs = 1;
    cudaLaunchKernelEx(&cfg, k, a...);
}

extern "C" void kernel_launch(void* const* d_in, const int* in_sizes, int n_in,
                              void* d_out, int out_size)
{
    const float* inputs  = (const float*)d_in[0];
    const int*   esrc    = (const int*)  d_in[1];
    const int*   edst    = (const int*)  d_in[2];
    const float* enter_w = (const float*)d_in[3];
    const float* enter_b = (const float*)d_in[4];
    const float* filt_w  = (const float*)d_in[5];
    const float* filt_b  = (const float*)d_in[6];
    const float* gate_w  = (const float*)d_in[7];
    const float* gate_b  = (const float*)d_in[8];
    const float* gc_w    = (const float*)d_in[9];
    const float* gc_b    = (const float*)d_in[10];
    const float* skip_w  = (const float*)d_in[11];
    const float* skip_b  = (const float*)d_in[12];
    const float* bn_g    = (const float*)d_in[13];
    const float* bn_b    = (const float*)d_in[14];
    const float* out1_w  = (const float*)d_in[15];
    const float* out1_b  = (const float*)d_in[16];
    const float* out2_w  = (const float*)d_in[17];
    const float* out2_b  = (const float*)d_in[18];
    float* out = (float*)d_out;

    static int attr_set = 0;
    if(!attr_set){
        cudaFuncSetAttribute(k_head, cudaFuncAttributeMaxDynamicSharedMemorySize, 25632*4);
        attr_set = 1;
    }

    float *xA, *xB, *hl;
    __half *pA, *pB, *hh;
    cudaGetSymbolAddress((void**)&xA, g_xA);
    cudaGetSymbolAddress((void**)&xB, g_xB);
    cudaGetSymbolAddress((void**)&pA, g_pA);
    cudaGetSymbolAddress((void**)&pB, g_pB);
    cudaGetSymbolAddress((void**)&hh, g_h);
    cudaGetSymbolAddress((void**)&hl, g_hl);

    const int GC = N_NODES/NPB;      // 2500
    const int GP = N_NODES/PW;       // 5000

    k_hist<<<(N_EDGES+255)/256, 256>>>(edst);
    k_trans<<<(512*256 + 24*512 + 255)/256, 256>>>(out1_w, out2_w);
    pdl(k_scan, 1, 1024, 0);

    pdl(k_fillconv, 1250 + GC, 256, conv_smem(true),
        esrc, edst, inputs, enter_w, enter_b,
        filt_w + 0*2048, filt_b + 0*32, gate_w + 0*2048, gate_b + 0*32,
        hl + 0*N_NODES*32, xA);
    pdl(k_hop<12>, GP, 128, (size_t)0, (const __half*)hh, pA);
    pdl(k_hop<12>, GP, 128, (size_t)0, (const __half*)pA, pB);
    pdl(k_propfin<12,13>, GP, 128, (size_t)0,
        (const __half*)pB, (const __half*)pA, gc_w + 0*4096,
        (const float*)xA, xB, gc_b + 0*32, bn_g + 0*32, bn_b + 0*32,
        1.f/((float)N_NODES*12.f));

#define LAYER(l, TIN, DD, XIN, XNEW)                                                         \
    {                                                                                        \
        const float t = (float)((TIN) - (DD));                                               \
        pdl(k_conv<TIN, DD, false, false>, GC, 256, conv_smem(false),                        \
            (const float*)XIN, (const float*)0, (const float*)0,                             \
            filt_w + (l)*2048, filt_b + (l)*32, gate_w + (l)*2048, gate_b + (l)*32,          \
            hl + (l)*N_NODES*32, (float*)0);                                                 \
        pdl(k_hop<(TIN)-(DD)>, GP, 128, (size_t)0, (const __half*)hh, pA);                   \
        pdl(k_hop<(TIN)-(DD)>, GP, 128, (size_t)0, (const __half*)pA, pB);                   \
        pdl(k_propfin<(TIN)-(DD), TIN>, GP, 128, (size_t)0,                                  \
            (const __half*)pB, (const __half*)pA, gc_w + (l)*4096,                           \
            (const float*)XIN, XNEW, gc_b + (l)*32, bn_g + (l)*32, bn_b + (l)*32,            \
            1.f/((float)N_NODES*t));                                                         \
    }

    LAYER(1, 12, 2, xB, xA)
    LAYER(2, 10, 1, xA, xB)
    LAYER(3,  9, 2, xB, xA)
    LAYER(4,  7, 1, xA, xB)
    LAYER(5,  6, 2, xB, xA)
    LAYER(6,  4, 1, xA, xB)
#undef LAYER

    // layer 7: conv + hl only
    pdl(k_conv<3,2,false,true>, GC, 256, conv_smem(false),
        (const float*)xB, (const float*)0, (const float*)0,
        filt_w + 7*2048, filt_b + 7*32, gate_w + 7*2048, gate_b + 7*32,
        hl + 7*N_NODES*32, (float*)0);

    pdl(k_head, N_NODES/16, 256, (size_t)(25632*4),
        skip_w, skip_b, out1_b, out2_b, out);
}

// round 15
// speedup vs baseline: 1.4078x; 1.1555x over previous
#include <cuda_runtime.h>
#include <cuda_fp16.h>
#include <math.h>

#define N_NODES 20000
#define N_EDGES 320000
#define NPB 8
#define PW 4      // warps (nodes) per prop block

#define GRID_WAIT() asm volatile("griddepcontrol.wait;" ::: "memory")

// ---------------- device scratch ----------------
__device__ float  g_xA[N_NODES*13*32];
__device__ float  g_xB[N_NODES*13*32];
__device__ __half g_h [N_NODES*12*32];
__device__ __half g_pA[N_NODES*12*32];
__device__ __half g_pB[N_NODES*12*32];
__device__ float  g_hl[8*N_NODES*32];
__device__ float  g_w1T[256*512];
__device__ float  g_w2T[512*24];
__device__ float4 g_wpk[8*1024];
__device__ int    g_rowptr[N_NODES+1];
__device__ int    g_curs[N_NODES];
__device__ int    g_cnt[N_NODES];
__device__ float  g_invdeg[N_NODES];
__device__ int    g_col[N_EDGES];
__device__ double g_statsS[32*64];
__device__ float  g_affine[64];
__device__ int    g_done;

__device__ __forceinline__ __half2 H2(unsigned int u){ return *reinterpret_cast<__half2*>(&u); }
__device__ __forceinline__ unsigned int U2(__half2 h){ return *reinterpret_cast<unsigned int*>(&h); }

// ---------------- packed f32x2 helpers ----------------
union Pun4 { float4 f; ulonglong2 u; };

__device__ __forceinline__ unsigned long long ffma2(unsigned long long a, unsigned long long b, unsigned long long c){
    unsigned long long d;
    asm("fma.rn.f32x2 %0, %1, %2, %3;" : "=l"(d) : "l"(a), "l"(b), "l"(c));
    return d;
}
__device__ __forceinline__ unsigned long long packf2(float lo, float hi){
    unsigned long long d;
    asm("mov.b64 %0, {%1, %2};" : "=l"(d) : "f"(lo), "f"(hi));
    return d;
}
__device__ __forceinline__ float2 unpackf2(unsigned long long v){
    float2 r;
    asm("mov.b64 {%0, %1}, %2;" : "=f"(r.x), "=f"(r.y) : "l"(v));
    return r;
}

// ---------------- setup ----------------
__global__ void k_hist(const int* __restrict__ dst){
    int i = blockIdx.x*256 + threadIdx.x;
    if(i < 64) g_affine[i] = (i < 32) ? 1.f : 0.f;
    if(i < N_EDGES) atomicAdd(&g_cnt[dst[i]], 1);
}

// transpose head weights + pack conv weights
__global__ void k_trans(const float* __restrict__ w1, const float* __restrict__ w2,
                        const float* __restrict__ filt_w, const float* __restrict__ gate_w){
    int idx = blockIdx.x*256 + threadIdx.x;
    if(idx < 512*256){
        int o = idx >> 8, c = idx & 255;
        g_w1T[c*512 + o] = w1[idx];
    }
    int j = idx - 512*256;
    if(j >= 0 && j < 24*512){
        int o = j >> 9, c = j & 511;
        g_w2T[c*24 + o] = w2[j];
    }
    int k = idx - (512*256 + 24*512);
    if(k >= 0 && k < 8*1024){
        int l = k >> 10, jj = k & 1023;
        int o = jj & 31, i = jj >> 5;
        const float* fw = filt_w + l*2048;
        const float* gw = gate_w + l*2048;
        float4 v;
        v.x = fw[(o*32+i)*2+0];
        v.y = fw[(o*32+i)*2+1];
        v.z = gw[(o*32+i)*2+0];
        v.w = gw[(o*32+i)*2+1];
        g_wpk[k] = v;
    }
}

__global__ void k_scan(){
    GRID_WAIT();
    const int CH = 20;
    int tid = threadIdx.x;
    int b0 = tid*CH; if(b0 > N_NODES) b0 = N_NODES;
    int b1 = b0 + CH; if(b1 > N_NODES) b1 = N_NODES;
    int sum = 0;
    for(int i = b0; i < b1; i++) sum += g_cnt[i];
    int lane = tid & 31, w = tid >> 5;
    int v = sum;
#pragma unroll
    for(int o = 1; o < 32; o <<= 1){
        int t = __shfl_up_sync(0xffffffffu, v, o);
        if(lane >= o) v += t;
    }
    __shared__ int wsum[32];
    if(lane == 31) wsum[w] = v;
    __syncthreads();
    if(w == 0){
        int x = wsum[lane];
#pragma unroll
        for(int o = 1; o < 32; o <<= 1){
            int t = __shfl_up_sync(0xffffffffu, x, o);
            if(lane >= o) x += t;
        }
        wsum[lane] = x;
    }
    __syncthreads();
    int pre = v - sum + ((w > 0) ? wsum[w-1] : 0);
    int run = pre;
    for(int i = b0; i < b1; i++){
        int c = g_cnt[i];
        g_curs[i] = run;
        run += c;
        g_rowptr[i+1] = run;
        g_invdeg[i] = 1.f/(float)(c > 0 ? c : 1);
        g_cnt[i] = 0;
    }
    if(tid == 0) g_rowptr[0] = 0;
}

// ---------------- conv body (flat 256 threads; 8 nodes): gated conv -> h(fp16), hl ----------------
template<int TIN, int D, bool ENTER, bool LAST>
__device__ __forceinline__ void conv_body(
    int n0, float* sm,
    const float* __restrict__ xin,
    const float* __restrict__ ew, const float* __restrict__ eb,
    const float4* __restrict__ wpk,
    const float* __restrict__ fb_g, const float* __restrict__ gb_g,
    float* __restrict__ hl_out, float* __restrict__ xsave)
{
    constexpr int TOUT = TIN - D;
    constexpr int NP2  = TOUT/2;
    constexpr int ODD  = TOUT & 1;
    constexpr int NQ   = (TIN + 3)/4;
    constexpr int TP   = 20;
    float* wq  = sm;
    float* ews = sm + 4096;
    float* xs  = ews + (ENTER ? 128 : 0);

    int tid = threadIdx.x;
    int tx = tid & 31, ty = tid >> 5;
    for(int j = tid; j < 1024; j += 256)
        ((float4*)wq)[j] = wpk[j];            // coalesced prepacked stage
    if(ENTER){
        if(tid < 96) ews[tid] = ew[tid];
        if(tid < 32) ews[96+tid] = eb[tid];
    }
    __syncthreads();
    GRID_WAIT();

    int n = n0 + ty;
    float* xrow = xs + ty*(32*TP);
    if(ENTER){
        const float* ip = xin + n*(TIN*3);
        float we0 = ews[tx*3+0], we1 = ews[tx*3+1], we2 = ews[tx*3+2], be = ews[96+tx];
#pragma unroll
        for(int tt = 0; tt < TIN; tt++){
            float v = be + we0*ip[tt*3+0] + we1*ip[tt*3+1] + we2*ip[tt*3+2];
            xrow[tx*TP+tt] = v;
            xsave[(n*TIN+tt)*32+tx] = v;
        }
    } else {
        float scl = g_affine[tx], bia = g_affine[32+tx];
        const float* xp = xin + n*(TIN*32);
#pragma unroll
        for(int tt = 0; tt < TIN; tt++)
            xrow[tx*TP+tt] = xp[tt*32+tx]*scl + bia;
    }
    __syncwarp();

    float fb = fb_g[tx], gb = gb_g[tx];
    unsigned long long f2[NP2 ? NP2 : 1], g2[NP2 ? NP2 : 1];
    {
        unsigned long long fbp = packf2(fb, fb), gbp = packf2(gb, gb);
#pragma unroll
        for(int j = 0; j < NP2; j++){ f2[j] = fbp; g2[j] = gbp; }
    }
    float fod = fb, god = gb;

#pragma unroll
    for(int i = 0; i < 32; i++){
        float4 w4 = ((const float4*)wq)[i*32+tx];
        unsigned long long W0f = packf2(w4.x, w4.x), W1f = packf2(w4.y, w4.y);
        unsigned long long W0g = packf2(w4.z, w4.z), W1g = packf2(w4.w, w4.w);
        Pun4 t4[NQ];
        const float4* xq = (const float4*)(xrow + i*TP);
#pragma unroll
        for(int q = 0; q < NQ; q++) t4[q].f = xq[q];
        float xv[NQ*4];
#pragma unroll
        for(int q = 0; q < NQ; q++){
            xv[q*4+0] = t4[q].f.x; xv[q*4+1] = t4[q].f.y;
            xv[q*4+2] = t4[q].f.z; xv[q*4+3] = t4[q].f.w;
        }
#pragma unroll
        for(int j = 0; j < NP2; j++){
            unsigned long long Aj = (j & 1) ? t4[j>>1].u.y : t4[j>>1].u.x;
            f2[j] = ffma2(Aj, W0f, f2[j]);
            g2[j] = ffma2(Aj, W0g, g2[j]);
            if(D & 1){
                unsigned long long Sj = packf2(xv[2*j+1], xv[2*j+2]);
                f2[j] = ffma2(Sj, W1f, f2[j]);
                g2[j] = ffma2(Sj, W1g, g2[j]);
            } else {
                int j1 = j + D/2;
                unsigned long long Aj1 = (j1 & 1) ? t4[j1>>1].u.y : t4[j1>>1].u.x;
                f2[j] = ffma2(Aj1, W1f, f2[j]);
                g2[j] = ffma2(Aj1, W1g, g2[j]);
            }
        }
        if(ODD){
            float x0 = xv[TOUT-1], x1 = xv[TOUT-1+D];
            fod += w4.x*x0 + w4.y*x1;
            god += w4.z*x0 + w4.w*x1;
        }
    }

    if(!LAST){
        float hlast = 0.f;
#pragma unroll
        for(int j = 0; j < NP2; j++){
            float2 ff = unpackf2(f2[j]);
            float2 gg = unpackf2(g2[j]);
            float h0 = tanhf(ff.x) * (1.f/(1.f + expf(-gg.x)));
            float h1 = tanhf(ff.y) * (1.f/(1.f + expf(-gg.y)));
            g_h[(n*TOUT + 2*j)*32+tx]   = __float2half_rn(h0);
            g_h[(n*TOUT + 2*j+1)*32+tx] = __float2half_rn(h1);
            if(2*j+1 == TOUT-1) hlast = h1;
        }
        if(ODD){
            float h = tanhf(fod) * (1.f/(1.f + expf(-god)));
            g_h[(n*TOUT + TOUT-1)*32+tx] = __float2half_rn(h);
            hlast = h;
        }
        hl_out[n*32+tx] = hlast;
    } else {
        float h = tanhf(fod) * (1.f/(1.f + expf(-god)));
        hl_out[n*32+tx] = h;
    }
}

template<int TIN, int D, bool ENTER, bool LAST>
__global__ void __launch_bounds__(256) k_conv(
    const float* __restrict__ xin,
    const float* __restrict__ ew, const float* __restrict__ eb,
    const float4* __restrict__ wpk,
    const float* __restrict__ fb_g, const float* __restrict__ gb_g,
    float* __restrict__ hl_out, float* __restrict__ xsave)
{
    extern __shared__ float sm[];
    conv_body<TIN,D,ENTER,LAST>(blockIdx.x*NPB, sm, xin, ew, eb,
        wpk, fb_g, gb_g, hl_out, xsave);
}

// fused: blocks [0,1250) do edge fill; rest do conv layer 0
__global__ void __launch_bounds__(256) k_fillconv(
    const int* __restrict__ src, const int* __restrict__ dst,
    const float* __restrict__ xin,
    const float* __restrict__ ew, const float* __restrict__ eb,
    const float4* __restrict__ wpk,
    const float* __restrict__ fb_g, const float* __restrict__ gb_g,
    float* __restrict__ hl_out, float* __restrict__ xsave)
{
    extern __shared__ float sm[];
    if(blockIdx.x < 1250){
        GRID_WAIT();
        int e = blockIdx.x*256 + threadIdx.x;
        if(e < N_EDGES){
            int pos = atomicAdd(&g_curs[dst[e]], 1);
            g_col[pos] = src[e];
        }
    } else {
        conv_body<13,1,true,false>((blockIdx.x-1250)*NPB, sm, xin, ew, eb,
            wpk, fb_g, gb_g, hl_out, xsave);
    }
}

// ---------------- fp16 gather core: one warp per node, contiguous edges ----------------
template<int T>
__device__ __forceinline__ void gather_row_h(const uint4* __restrict__ in,
                                             int n, int lane, float* acc)
{
    constexpr int R  = T*4;
    constexpr int NV = (R + 31)/32;
    constexpr int EG = (NV == 1) ? 8 : 4;
#pragma unroll
    for(int k = 0; k < NV*8; k++) acc[k] = 0.f;
    int beg = g_rowptr[n], end = g_rowptr[n+1];
    int e = beg;
    for(; e + EG <= end; e += EG){
        int s[EG];
#pragma unroll
        for(int j = 0; j < EG; j++) s[j] = g_col[e+j];
        uint4 q[EG*NV];
#pragma unroll
        for(int j = 0; j < EG; j++){
#pragma unroll
            for(int v = 0; v < NV; v++){
                int idx = v*32 + lane;
                if(idx < R) q[j*NV+v] = in[s[j]*R + idx];
            }
        }
#pragma unroll
        for(int v = 0; v < NV; v++){
            int idx = v*32 + lane;
            if(idx < R){
                __half2 tx_[EG], ty_[EG], tz_[EG], tw_[EG];
#pragma unroll
                for(int j = 0; j < EG; j++){
                    tx_[j] = H2(q[j*NV+v].x); ty_[j] = H2(q[j*NV+v].y);
                    tz_[j] = H2(q[j*NV+v].z); tw_[j] = H2(q[j*NV+v].w);
                }
#pragma unroll
                for(int st = 1; st < EG; st <<= 1){
#pragma unroll
                    for(int j = 0; j < EG; j += 2*st){
                        tx_[j] = __hadd2(tx_[j], tx_[j+st]);
                        ty_[j] = __hadd2(ty_[j], ty_[j+st]);
                        tz_[j] = __hadd2(tz_[j], tz_[j+st]);
                        tw_[j] = __hadd2(tw_[j], tw_[j+st]);
                    }
                }
                float2 f;
                f = __half22float2(tx_[0]); acc[v*8+0] += f.x; acc[v*8+1] += f.y;
                f = __half22float2(ty_[0]); acc[v*8+2] += f.x; acc[v*8+3] += f.y;
                f = __half22float2(tz_[0]); acc[v*8+4] += f.x; acc[v*8+5] += f.y;
                f = __half22float2(tw_[0]); acc[v*8+6] += f.x; acc[v*8+7] += f.y;
            }
        }
    }
    for(; e < end; e++){
        int s0 = g_col[e];
        const uint4* r0 = in + s0*R;
#pragma unroll
        for(int v = 0; v < NV; v++){
            int idx = v*32 + lane;
            if(idx < R){
                uint4 q = r0[idx];
                float2 f;
                f = __half22float2(H2(q.x)); acc[v*8+0] += f.x; acc[v*8+1] += f.y;
                f = __half22float2(H2(q.y)); acc[v*8+2] += f.x; acc[v*8+3] += f.y;
                f = __half22float2(H2(q.z)); acc[v*8+4] += f.x; acc[v*8+5] += f.y;
                f = __half22float2(H2(q.w)); acc[v*8+6] += f.x; acc[v*8+7] += f.y;
            }
        }
    }
    float iv = g_invdeg[n];
#pragma unroll
    for(int k = 0; k < NV*8; k++) acc[k] *= iv;
}

// scatter gathered fp32 values into smem tile (t-major, 32 ch)
template<int T>
__device__ __forceinline__ void acc_to_tile(const float* acc, float* tile, int lane){
    constexpr int R  = T*4;
    constexpr int NV = (R + 31)/32;
#pragma unroll
    for(int v = 0; v < NV; v++){
        int idx = v*32 + lane;
        if(idx < R){
            int t = idx >> 2, c0 = (idx & 3) << 3;
            float4* tp = (float4*)(tile + t*32 + c0);
            tp[0] = make_float4(acc[v*8+0], acc[v*8+1], acc[v*8+2], acc[v*8+3]);
            tp[1] = make_float4(acc[v*8+4], acc[v*8+5], acc[v*8+6], acc[v*8+7]);
        }
    }
}

// load an fp16 row (own node, coalesced) into the fp32 smem tile
template<int T>
__device__ __forceinline__ void row_to_tile(const __half* __restrict__ row,
                                            float* tile, int lane){
    constexpr int R  = T*4;
    constexpr int NV = (R + 31)/32;
    const uint4* r4 = (const uint4*)row;
#pragma unroll
    for(int v = 0; v < NV; v++){
        int idx = v*32 + lane;
        if(idx < R){
            uint4 q = r4[idx];
            int t = idx >> 2, c0 = (idx & 3) << 3;
            float4* tp = (float4*)(tile + t*32 + c0);
            float2 fx = __half22float2(H2(q.x));
            float2 fy = __half22float2(H2(q.y));
            float2 fz = __half22float2(H2(q.z));
            float2 fw = __half22float2(H2(q.w));
            tp[0] = make_float4(fx.x, fx.y, fy.x, fy.y);
            tp[1] = make_float4(fz.x, fz.y, fw.x, fw.y);
        }
    }
}

// packed GEMM: a2[t] += pairs over K of tile[t][c] * W[c][lane]
template<int T>
__device__ __forceinline__ void gemm_acc2(const float* tile, const float* Ws,
                                          int lane, unsigned long long* a2){
#pragma unroll
    for(int c4 = 0; c4 < 8; c4++){
        unsigned long long W01 = packf2(Ws[(c4*4+0)*32+lane], Ws[(c4*4+1)*32+lane]);
        unsigned long long W23 = packf2(Ws[(c4*4+2)*32+lane], Ws[(c4*4+3)*32+lane]);
#pragma unroll
        for(int t = 0; t < T; t++){
            const ulonglong2* rp = (const ulonglong2*)(tile + t*32 + c4*4);
            ulonglong2 sv = *rp;
            a2[t] = ffma2(sv.x, W01, a2[t]);
            a2[t] = ffma2(sv.y, W23, a2[t]);
        }
    }
}

// store gathered acc as fp16 row
template<int T>
__device__ __forceinline__ void acc_store_h(const float* acc, __half* out, int n, int lane){
    constexpr int R  = T*4;
    constexpr int NV = (R + 31)/32;
    uint4* cp = (uint4*)out + n*R;
#pragma unroll
    for(int v = 0; v < NV; v++){
        int idx = v*32 + lane;
        if(idx < R){
            uint4 q;
            q.x = U2(__floats2half2_rn(acc[v*8+0], acc[v*8+1]));
            q.y = U2(__floats2half2_rn(acc[v*8+2], acc[v*8+3]));
            q.z = U2(__floats2half2_rn(acc[v*8+4], acc[v*8+5]));
            q.w = U2(__floats2half2_rn(acc[v*8+6], acc[v*8+7]));
            cp[idx] = q;
        }
    }
}

// ---------------- pure diffusion hop: out = A*in (fp16 -> fp16) ----------------
template<int T>
__global__ void __launch_bounds__(128) k_hop(
    const __half* __restrict__ in, __half* __restrict__ out)
{
    GRID_WAIT();
    constexpr int NV = (T*4 + 31)/32;
    int tid = threadIdx.x, lane = tid & 31, wid = tid >> 5;
    int n = blockIdx.x*PW + wid;
    float acc[NV*8];
    gather_row_h<T>((const uint4*)in, n, lane, acc);
    acc_store_h<T>(acc, out, n, lane);
}

// ---------------- propfin: p3 = A*p2 ; x = h@W0+p1@W1+p2@W2+p3@W3 + gcb + affine(xold); BN ----------------
template<int T, int TIN>
__global__ void __launch_bounds__(128) k_propfin(
    const __half* __restrict__ in,        // p2
    const __half* __restrict__ p1,
    const float* __restrict__ Wk4,        // 4x 32x32
    const float* __restrict__ xold, float* __restrict__ xnew,
    const float* __restrict__ gcb,
    const float* __restrict__ bng, const float* __restrict__ bnb, float invCnt)
{
    constexpr int NV = (T*4 + 31)/32;
    __shared__ float Ws[4096];
    __shared__ __align__(16) float smS[PW*12*32];
    __shared__ float rs[32*PW], rq[32*PW];
    __shared__ int isLast;
    int tid = threadIdx.x, lane = tid & 31, wid = tid >> 5;
    for(int j = tid; j < 4096; j += 128) Ws[j] = Wk4[j];
    __syncthreads();
    GRID_WAIT();

    int n = blockIdx.x*PW + wid;
    float acc[NV*8];
    gather_row_h<T>((const uint4*)in, n, lane, acc);   // p3

    unsigned long long a2[T];
#pragma unroll
    for(int t = 0; t < T; t++) a2[t] = 0ull;
    float* tile = smS + wid*(T*32);

    row_to_tile<T>(g_h + n*(T*32), tile, lane);  __syncwarp();
    gemm_acc2<T>(tile, Ws,        lane, a2);     __syncwarp();
    row_to_tile<T>(p1 + n*(T*32), tile, lane);   __syncwarp();
    gemm_acc2<T>(tile, Ws + 1024, lane, a2);     __syncwarp();
    row_to_tile<T>(in + n*(T*32), tile, lane);   __syncwarp();
    gemm_acc2<T>(tile, Ws + 2048, lane, a2);     __syncwarp();
    acc_to_tile<T>(acc, tile, lane);             __syncwarp();
    gemm_acc2<T>(tile, Ws + 3072, lane, a2);

    float scl = g_affine[lane], bia = g_affine[32+lane];
    float gb  = gcb[lane];
    const float* xo = xold + (n*TIN + (TIN-T))*32 + lane;
    float* xn = xnew + n*(T*32) + lane;
    float sum = 0.f, sq = 0.f;
#pragma unroll
    for(int t = 0; t < T; t++){
        float2 av = unpackf2(a2[t]);
        float v = (av.x + av.y) + gb + xo[t*32]*scl + bia;
        xn[t*32] = v;
        sum += v; sq += v*v;
    }
    rs[tid] = sum; rq[tid] = sq;
    __syncthreads();
    if(tid < 32){
        float ts = 0.f, tq = 0.f;
#pragma unroll
        for(int w = 0; w < PW; w++){ ts += rs[w*32+tid]; tq += rq[w*32+tid]; }
        int sh = (blockIdx.x & 31)*64;
        atomicAdd(&g_statsS[sh+tid],    (double)ts);
        atomicAdd(&g_statsS[sh+32+tid], (double)tq);
    }
    if(tid == 0){
        __threadfence();
        int d = atomicAdd(&g_done, 1);
        isLast = (d == (int)gridDim.x - 1) ? 1 : 0;
    }
    __syncthreads();
    if(isLast){
        __threadfence();
        if(tid < 32){
            double S = 0.0, Q = 0.0;
            for(int k = 0; k < 32; k++){ S += g_statsS[k*64+tid]; Q += g_statsS[k*64+32+tid]; }
            double mu  = S*(double)invCnt;
            double var = Q*(double)invCnt - mu*mu;
            if(var < 0.0) var = 0.0;
            float scale = bng[tid] * rsqrtf((float)var + 1e-5f);
            g_affine[tid]    = scale;
            g_affine[32+tid] = bnb[tid] - (float)mu*scale;
        }
        __syncthreads();
        for(int j = tid; j < 2048; j += 128) g_statsS[j] = 0.0;
        if(tid == 0) g_done = 0;
    }
}

// ---------------- head (f32x2 packed, transposed weights) ----------------
__global__ void __launch_bounds__(256) k_head(
    const float* __restrict__ sw_g, const float* __restrict__ sb_g,
    const float* __restrict__ b1, const float* __restrict__ b2,
    float* __restrict__ out)
{
    GRID_WAIT();
    extern __shared__ float sm[];
    float* hlsT    = sm;
    float* skipacc = sm + 5120;
    float* wbuf    = sm + 9216;
    float* y1s     = sm + 17440;
    int tid = threadIdx.x;
    int n0 = blockIdx.x*16;

    for(int j = tid; j < 8*16*32; j += 256){
        int c = j & 31, m = (j>>5) & 15, l = j>>9;
        hlsT[(l*32+c)*20 + m] = g_hl[l*(N_NODES*32) + (n0+m)*32 + c];
    }
    unsigned long long a2m[8];
    {
        float bs = 0.f;
        for(int l = 0; l < 8; l++) bs += sb_g[l*256+tid];
        unsigned long long bsp = packf2(bs, bs);
#pragma unroll
        for(int j = 0; j < 8; j++) a2m[j] = bsp;
    }
    for(int l = 0; l < 8; l++){
        __syncthreads();
        for(int j = tid; j < 8192; j += 256){
            int c = j & 31, O = j >> 5;
            wbuf[c*257+O] = sw_g[l*8192 + O*32 + c];
        }
        __syncthreads();
#pragma unroll 4
        for(int c = 0; c < 32; c++){
            float w = wbuf[c*257+tid];
            unsigned long long W = packf2(w, w);
            const ulonglong2* hp = (const ulonglong2*)(hlsT + (l*32+c)*20);
#pragma unroll
            for(int m4 = 0; m4 < 4; m4++){
                ulonglong2 h2 = hp[m4];
                a2m[m4*2+0] = ffma2(h2.x, W, a2m[m4*2+0]);
                a2m[m4*2+1] = ffma2(h2.y, W, a2m[m4*2+1]);
            }
        }
    }
    __syncthreads();
#pragma unroll
    for(int j = 0; j < 8; j++){
        float2 v = unpackf2(a2m[j]);
        skipacc[(2*j)*256+tid]   = fmaxf(v.x, 0.f);
        skipacc[(2*j+1)*256+tid] = fmaxf(v.y, 0.f);
    }
    __syncthreads();

    for(int oo = 0; oo < 2; oo++){
        int o = oo*256 + tid;
        unsigned long long acc2[16];
#pragma unroll
        for(int m = 0; m < 16; m++) acc2[m] = 0ull;
        const ulonglong2* sa = (const ulonglong2*)skipacc;
        for(int c4 = 0; c4 < 64; c4++){
            float wa = g_w1T[(c4*4+0)*512 + o];
            float wb = g_w1T[(c4*4+1)*512 + o];
            float wc = g_w1T[(c4*4+2)*512 + o];
            float wd = g_w1T[(c4*4+3)*512 + o];
            unsigned long long Wab = packf2(wa, wb);
            unsigned long long Wcd = packf2(wc, wd);
#pragma unroll
            for(int m = 0; m < 16; m++){
                ulonglong2 s = sa[m*64 + c4];
                acc2[m] = ffma2(s.x, Wab, acc2[m]);
                acc2[m] = ffma2(s.y, Wcd, acc2[m]);
            }
        }
        float bb = b1[o];
#pragma unroll
        for(int m = 0; m < 16; m++){
            float2 v = unpackf2(acc2[m]);
            y1s[m*512+o] = fmaxf(v.x + v.y + bb, 0.f);
        }
    }
    __syncthreads();

    for(int idx = tid; idx < 16*24; idx += 256){
        int m = idx/24, o = idx - 24*m;
        unsigned long long acc2 = 0ull;
        const ulonglong2* yp = (const ulonglong2*)(y1s + m*512);
        for(int c4 = 0; c4 < 128; c4++){
            float wa = g_w2T[(c4*4+0)*24 + o];
            float wb = g_w2T[(c4*4+1)*24 + o];
            float wc = g_w2T[(c4*4+2)*24 + o];
            float wd = g_w2T[(c4*4+3)*24 + o];
            ulonglong2 yy = yp[c4];
            acc2 = ffma2(yy.x, packf2(wa, wb), acc2);
            acc2 = ffma2(yy.y, packf2(wc, wd), acc2);
        }
        float2 v = unpackf2(acc2);
        out[(n0+m)*24 + o] = b2[o] + v.x + v.y;
    }
}

// ---------------- host ----------------
static inline size_t conv_smem(bool enter){
    return (size_t)(4096 + (enter ? 128 : 0) + NPB*32*20) * 4;
}

template<class K, class... A>
static inline void pdl(K k, int grid, int block, size_t smem, A... a){
    cudaLaunchConfig_t cfg;
    memset(&cfg, 0, sizeof(cfg));
    cfg.gridDim  = dim3((unsigned)grid, 1, 1);
    cfg.blockDim = dim3((unsigned)block, 1, 1);
    cfg.dynamicSmemBytes = smem;
    cfg.stream = 0;
    cudaLaunchAttribute at;
    at.id = cudaLaunchAttributeProgrammaticStreamSerialization;
    at.val.programmaticStreamSerializationAllowed = 1;
    cfg.attrs = &at;
    cfg.numAttrs = 1;
    cudaLaunchKernelEx(&cfg, k, a...);
}

extern "C" void kernel_launch(void* const* d_in, const int* in_sizes, int n_in,
                              void* d_out, int out_size)
{
    const float* inputs  = (const float*)d_in[0];
    const int*   esrc    = (const int*)  d_in[1];
    const int*   edst    = (const int*)  d_in[2];
    const float* enter_w = (const float*)d_in[3];
    const float* enter_b = (const float*)d_in[4];
    const float* filt_w  = (const float*)d_in[5];
    const float* filt_b  = (const float*)d_in[6];
    const float* gate_w  = (const float*)d_in[7];
    const float* gate_b  = (const float*)d_in[8];
    const float* gc_w    = (const float*)d_in[9];
    const float* gc_b    = (const float*)d_in[10];
    const float* skip_w  = (const float*)d_in[11];
    const float* skip_b  = (const float*)d_in[12];
    const float* bn_g    = (const float*)d_in[13];
    const float* bn_b    = (const float*)d_in[14];
    const float* out1_w  = (const float*)d_in[15];
    const float* out1_b  = (const float*)d_in[16];
    const float* out2_w  = (const float*)d_in[17];
    const float* out2_b  = (const float*)d_in[18];
    float* out = (float*)d_out;

    static int attr_set = 0;
    if(!attr_set){
        cudaFuncSetAttribute(k_head, cudaFuncAttributeMaxDynamicSharedMemorySize, 25632*4);
        attr_set = 1;
    }

    float *xA, *xB, *hl;
    __half *pA, *pB, *hh;
    float4 *wpk;
    cudaGetSymbolAddress((void**)&xA, g_xA);
    cudaGetSymbolAddress((void**)&xB, g_xB);
    cudaGetSymbolAddress((void**)&pA, g_pA);
    cudaGetSymbolAddress((void**)&pB, g_pB);
    cudaGetSymbolAddress((void**)&hh, g_h);
    cudaGetSymbolAddress((void**)&hl, g_hl);
    cudaGetSymbolAddress((void**)&wpk, g_wpk);

    const int GC = N_NODES/NPB;      // 2500
    const int GP = N_NODES/PW;       // 5000

    k_hist<<<(N_EDGES+255)/256, 256>>>(edst);
    k_trans<<<(512*256 + 24*512 + 8*1024 + 255)/256, 256>>>(out1_w, out2_w, filt_w, gate_w);
    pdl(k_scan, 1, 1024, 0);

    pdl(k_fillconv, 1250 + GC, 256, conv_smem(true),
        esrc, edst, inputs, enter_w, enter_b,
        (const float4*)(wpk + 0*1024), filt_b + 0*32, gate_b + 0*32,
        hl + 0*N_NODES*32, xA);
    pdl(k_hop<12>, GP, 128, (size_t)0, (const __half*)hh, pA);
    pdl(k_hop<12>, GP, 128, (size_t)0, (const __half*)pA, pB);
    pdl(k_propfin<12,13>, GP, 128, (size_t)0,
        (const __half*)pB, (const __half*)pA, gc_w + 0*4096,
        (const float*)xA, xB, gc_b + 0*32, bn_g + 0*32, bn_b + 0*32,
        1.f/((float)N_NODES*12.f));

#define LAYER(l, TIN, DD, XIN, XNEW)                                                         \
    {                                                                                        \
        const float t = (float)((TIN) - (DD));                                               \
        pdl(k_conv<TIN, DD, false, false>, GC, 256, conv_smem(false),                        \
            (const float*)XIN, (const float*)0, (const float*)0,                             \
            (const float4*)(wpk + (l)*1024), filt_b + (l)*32, gate_b + (l)*32,               \
            hl + (l)*N_NODES*32, (float*)0);                                                 \
        pdl(k_hop<(TIN)-(DD)>, GP, 128, (size_t)0, (const __half*)hh, pA);                   \
        pdl(k_hop<(TIN)-(DD)>, GP, 128, (size_t)0, (const __half*)pA, pB);                   \
        pdl(k_propfin<(TIN)-(DD), TIN>, GP, 128, (size_t)0,                                  \
            (const __half*)pB, (const __half*)pA, gc_w + (l)*4096,                           \
            (const float*)XIN, XNEW, gc_b + (l)*32, bn_g + (l)*32, bn_b + (l)*32,            \
            1.f/((float)N_NODES*t));                                                         \
    }

    LAYER(1, 12, 2, xB, xA)
    LAYER(2, 10, 1, xA, xB)
    LAYER(3,  9, 2, xB, xA)
    LAYER(4,  7, 1, xA, xB)
    LAYER(5,  6, 2, xB, xA)
    LAYER(6,  4, 1, xA, xB)
#undef LAYER

    // layer 7: conv + hl only
    pdl(k_conv<3,2,false,true>, GC, 256, conv_smem(false),
        (const float*)xB, (const float*)0, (const float*)0,
        (const float4*)(wpk + 7*1024), filt_b + 7*32, gate_b + 7*32,
        hl + 7*N_NODES*32, (float*)0);

    pdl(k_head, N_NODES/16, 256, (size_t)(25632*4),
        skip_w, skip_b, out1_b, out2_b, out);
}

// round 16
// speedup vs baseline: 1.4079x; 1.0000x over previous
#include <cuda_runtime.h>
#include <cuda_fp16.h>
#include <math.h>

#define N_NODES 20000
#define N_EDGES 320000
#define NPB 8
#define PW 4      // warps (nodes) per prop block

#define GRID_WAIT() asm volatile("griddepcontrol.wait;" ::: "memory")

// ---------------- device scratch ----------------
__device__ float  g_xA[N_NODES*13*32];
__device__ float  g_xB[N_NODES*13*32];
__device__ __half g_h [N_NODES*12*32];
__device__ __half g_pA[N_NODES*12*32];
__device__ __half g_pB[N_NODES*12*32];
__device__ float  g_hl[8*N_NODES*32];
__device__ float  g_w1T[256*512];
__device__ float  g_w2T[512*24];
__device__ float4 g_wpk[8*1024];
__device__ int    g_rowptr[N_NODES+1];
__device__ int    g_curs[N_NODES];
__device__ int    g_cnt[N_NODES];
__device__ float  g_invdeg[N_NODES];
__device__ int    g_col[N_EDGES];
__device__ double g_statsS[32*64];
__device__ float  g_affine[64];
__device__ int    g_done;

__device__ __forceinline__ __half2 H2(unsigned int u){ return *reinterpret_cast<__half2*>(&u); }
__device__ __forceinline__ unsigned int U2(__half2 h){ return *reinterpret_cast<unsigned int*>(&h); }

// ---------------- packed f32x2 helpers ----------------
union Pun4 { float4 f; ulonglong2 u; };

__device__ __forceinline__ unsigned long long ffma2(unsigned long long a, unsigned long long b, unsigned long long c){
    unsigned long long d;
    asm("fma.rn.f32x2 %0, %1, %2, %3;" : "=l"(d) : "l"(a), "l"(b), "l"(c));
    return d;
}
__device__ __forceinline__ unsigned long long packf2(float lo, float hi){
    unsigned long long d;
    asm("mov.b64 %0, {%1, %2};" : "=l"(d) : "f"(lo), "f"(hi));
    return d;
}
__device__ __forceinline__ float2 unpackf2(unsigned long long v){
    float2 r;
    asm("mov.b64 {%0, %1}, %2;" : "=f"(r.x), "=f"(r.y) : "l"(v));
    return r;
}

// ---------------- setup ----------------
__global__ void k_hist(const int* __restrict__ dst){
    int i = blockIdx.x*256 + threadIdx.x;
    if(i < 64) g_affine[i] = (i < 32) ? 1.f : 0.f;
    if(i < N_EDGES) atomicAdd(&g_cnt[dst[i]], 1);
}

// transpose head weights + pack conv weights
__global__ void k_trans(const float* __restrict__ w1, const float* __restrict__ w2,
                        const float* __restrict__ filt_w, const float* __restrict__ gate_w){
    int idx = blockIdx.x*256 + threadIdx.x;
    if(idx < 512*256){
        int o = idx >> 8, c = idx & 255;
        g_w1T[c*512 + o] = w1[idx];
    }
    int j = idx - 512*256;
    if(j >= 0 && j < 24*512){
        int o = j >> 9, c = j & 511;
        g_w2T[c*24 + o] = w2[j];
    }
    int k = idx - (512*256 + 24*512);
    if(k >= 0 && k < 8*1024){
        int l = k >> 10, jj = k & 1023;
        int o = jj & 31, i = jj >> 5;
        const float* fw = filt_w + l*2048;
        const float* gw = gate_w + l*2048;
        float4 v;
        v.x = fw[(o*32+i)*2+0];
        v.y = fw[(o*32+i)*2+1];
        v.z = gw[(o*32+i)*2+0];
        v.w = gw[(o*32+i)*2+1];
        g_wpk[k] = v;
    }
}

__global__ void k_scan(){
    GRID_WAIT();
    const int CH = 20;
    int tid = threadIdx.x;
    int b0 = tid*CH; if(b0 > N_NODES) b0 = N_NODES;
    int b1 = b0 + CH; if(b1 > N_NODES) b1 = N_NODES;
    int sum = 0;
    for(int i = b0; i < b1; i++) sum += g_cnt[i];
    int lane = tid & 31, w = tid >> 5;
    int v = sum;
#pragma unroll
    for(int o = 1; o < 32; o <<= 1){
        int t = __shfl_up_sync(0xffffffffu, v, o);
        if(lane >= o) v += t;
    }
    __shared__ int wsum[32];
    if(lane == 31) wsum[w] = v;
    __syncthreads();
    if(w == 0){
        int x = wsum[lane];
#pragma unroll
        for(int o = 1; o < 32; o <<= 1){
            int t = __shfl_up_sync(0xffffffffu, x, o);
            if(lane >= o) x += t;
        }
        wsum[lane] = x;
    }
    __syncthreads();
    int pre = v - sum + ((w > 0) ? wsum[w-1] : 0);
    int run = pre;
    for(int i = b0; i < b1; i++){
        int c = g_cnt[i];
        g_curs[i] = run;
        run += c;
        g_rowptr[i+1] = run;
        g_invdeg[i] = 1.f/(float)(c > 0 ? c : 1);
        g_cnt[i] = 0;
    }
    if(tid == 0) g_rowptr[0] = 0;
}

// ---------------- conv body (flat 256 threads; 8 nodes): gated conv -> h(fp16), hl ----------------
template<int TIN, int D, bool ENTER, bool LAST>
__device__ __forceinline__ void conv_body(
    int n0, float* sm,
    const float* __restrict__ xin,
    const float* __restrict__ ew, const float* __restrict__ eb,
    const float4* __restrict__ wpk,
    const float* __restrict__ fb_g, const float* __restrict__ gb_g,
    float* __restrict__ hl_out, float* __restrict__ xsave)
{
    constexpr int TOUT = TIN - D;
    constexpr int NP2  = TOUT/2;
    constexpr int ODD  = TOUT & 1;
    constexpr int NQ   = (TIN + 3)/4;
    constexpr int TP   = 20;
    float* wq  = sm;
    float* ews = sm + 4096;
    float* xs  = ews + (ENTER ? 128 : 0);

    int tid = threadIdx.x;
    int tx = tid & 31, ty = tid >> 5;
    for(int j = tid; j < 1024; j += 256)
        ((float4*)wq)[j] = wpk[j];            // coalesced prepacked stage
    if(ENTER){
        if(tid < 96) ews[tid] = ew[tid];
        if(tid < 32) ews[96+tid] = eb[tid];
    }
    __syncthreads();
    GRID_WAIT();

    int n = n0 + ty;
    float* xrow = xs + ty*(32*TP);
    if(ENTER){
        const float* ip = xin + n*(TIN*3);
        float we0 = ews[tx*3+0], we1 = ews[tx*3+1], we2 = ews[tx*3+2], be = ews[96+tx];
#pragma unroll
        for(int tt = 0; tt < TIN; tt++){
            float v = be + we0*ip[tt*3+0] + we1*ip[tt*3+1] + we2*ip[tt*3+2];
            xrow[tx*TP+tt] = v;
            xsave[(n*TIN+tt)*32+tx] = v;
        }
    } else {
        float scl = g_affine[tx], bia = g_affine[32+tx];
        const float* xp = xin + n*(TIN*32);
#pragma unroll
        for(int tt = 0; tt < TIN; tt++)
            xrow[tx*TP+tt] = xp[tt*32+tx]*scl + bia;
    }
    __syncwarp();

    float fb = fb_g[tx], gb = gb_g[tx];
    unsigned long long f2[NP2 ? NP2 : 1], g2[NP2 ? NP2 : 1];
    {
        unsigned long long fbp = packf2(fb, fb), gbp = packf2(gb, gb);
#pragma unroll
        for(int j = 0; j < NP2; j++){ f2[j] = fbp; g2[j] = gbp; }
    }
    float fod = fb, god = gb;

#pragma unroll
    for(int i = 0; i < 32; i++){
        float4 w4 = ((const float4*)wq)[i*32+tx];
        unsigned long long W0f = packf2(w4.x, w4.x), W1f = packf2(w4.y, w4.y);
        unsigned long long W0g = packf2(w4.z, w4.z), W1g = packf2(w4.w, w4.w);
        Pun4 t4[NQ];
        const float4* xq = (const float4*)(xrow + i*TP);
#pragma unroll
        for(int q = 0; q < NQ; q++) t4[q].f = xq[q];
        float xv[NQ*4];
#pragma unroll
        for(int q = 0; q < NQ; q++){
            xv[q*4+0] = t4[q].f.x; xv[q*4+1] = t4[q].f.y;
            xv[q*4+2] = t4[q].f.z; xv[q*4+3] = t4[q].f.w;
        }
#pragma unroll
        for(int j = 0; j < NP2; j++){
            unsigned long long Aj = (j & 1) ? t4[j>>1].u.y : t4[j>>1].u.x;
            f2[j] = ffma2(Aj, W0f, f2[j]);
            g2[j] = ffma2(Aj, W0g, g2[j]);
            if(D & 1){
                unsigned long long Sj = packf2(xv[2*j+1], xv[2*j+2]);
                f2[j] = ffma2(Sj, W1f, f2[j]);
                g2[j] = ffma2(Sj, W1g, g2[j]);
            } else {
                int j1 = j + D/2;
                unsigned long long Aj1 = (j1 & 1) ? t4[j1>>1].u.y : t4[j1>>1].u.x;
                f2[j] = ffma2(Aj1, W1f, f2[j]);
                g2[j] = ffma2(Aj1, W1g, g2[j]);
            }
        }
        if(ODD){
            float x0 = xv[TOUT-1], x1 = xv[TOUT-1+D];
            fod += w4.x*x0 + w4.y*x1;
            god += w4.z*x0 + w4.w*x1;
        }
    }

    if(!LAST){
        float hlast = 0.f;
#pragma unroll
        for(int j = 0; j < NP2; j++){
            float2 ff = unpackf2(f2[j]);
            float2 gg = unpackf2(g2[j]);
            float h0 = tanhf(ff.x) * (1.f/(1.f + expf(-gg.x)));
            float h1 = tanhf(ff.y) * (1.f/(1.f + expf(-gg.y)));
            g_h[(n*TOUT + 2*j)*32+tx]   = __float2half_rn(h0);
            g_h[(n*TOUT + 2*j+1)*32+tx] = __float2half_rn(h1);
            if(2*j+1 == TOUT-1) hlast = h1;
        }
        if(ODD){
            float h = tanhf(fod) * (1.f/(1.f + expf(-god)));
            g_h[(n*TOUT + TOUT-1)*32+tx] = __float2half_rn(h);
            hlast = h;
        }
        hl_out[n*32+tx] = hlast;
    } else {
        float h = tanhf(fod) * (1.f/(1.f + expf(-god)));
        hl_out[n*32+tx] = h;
    }
}

template<int TIN, int D, bool ENTER, bool LAST>
__global__ void __launch_bounds__(256) k_conv(
    const float* __restrict__ xin,
    const float* __restrict__ ew, const float* __restrict__ eb,
    const float4* __restrict__ wpk,
    const float* __restrict__ fb_g, const float* __restrict__ gb_g,
    float* __restrict__ hl_out, float* __restrict__ xsave)
{
    extern __shared__ float sm[];
    conv_body<TIN,D,ENTER,LAST>(blockIdx.x*NPB, sm, xin, ew, eb,
        wpk, fb_g, gb_g, hl_out, xsave);
}

// fused: blocks [0,1250) do edge fill; rest do conv layer 0
__global__ void __launch_bounds__(256) k_fillconv(
    const int* __restrict__ src, const int* __restrict__ dst,
    const float* __restrict__ xin,
    const float* __restrict__ ew, const float* __restrict__ eb,
    const float4* __restrict__ wpk,
    const float* __restrict__ fb_g, const float* __restrict__ gb_g,
    float* __restrict__ hl_out, float* __restrict__ xsave)
{
    extern __shared__ float sm[];
    if(blockIdx.x < 1250){
        GRID_WAIT();
        int e = blockIdx.x*256 + threadIdx.x;
        if(e < N_EDGES){
            int pos = atomicAdd(&g_curs[dst[e]], 1);
            g_col[pos] = src[e];
        }
    } else {
        conv_body<13,1,true,false>((blockIdx.x-1250)*NPB, sm, xin, ew, eb,
            wpk, fb_g, gb_g, hl_out, xsave);
    }
}

// ---------------- fp16 gather core: one warp per node, contiguous edges ----------------
template<int T>
__device__ __forceinline__ void gather_row_h(const uint4* __restrict__ in,
                                             int n, int lane, float* acc)
{
    constexpr int R  = T*4;
    constexpr int NV = (R + 31)/32;
    constexpr int EG = (NV == 1) ? 8 : 4;
#pragma unroll
    for(int k = 0; k < NV*8; k++) acc[k] = 0.f;
    int beg = g_rowptr[n], end = g_rowptr[n+1];
    int e = beg;
    for(; e + EG <= end; e += EG){
        int s[EG];
#pragma unroll
        for(int j = 0; j < EG; j++) s[j] = g_col[e+j];
        uint4 q[EG*NV];
#pragma unroll
        for(int j = 0; j < EG; j++){
#pragma unroll
            for(int v = 0; v < NV; v++){
                int idx = v*32 + lane;
                if(idx < R) q[j*NV+v] = in[s[j]*R + idx];
            }
        }
#pragma unroll
        for(int v = 0; v < NV; v++){
            int idx = v*32 + lane;
            if(idx < R){
                __half2 tx_[EG], ty_[EG], tz_[EG], tw_[EG];
#pragma unroll
                for(int j = 0; j < EG; j++){
                    tx_[j] = H2(q[j*NV+v].x); ty_[j] = H2(q[j*NV+v].y);
                    tz_[j] = H2(q[j*NV+v].z); tw_[j] = H2(q[j*NV+v].w);
                }
#pragma unroll
                for(int st = 1; st < EG; st <<= 1){
#pragma unroll
                    for(int j = 0; j < EG; j += 2*st){
                        tx_[j] = __hadd2(tx_[j], tx_[j+st]);
                        ty_[j] = __hadd2(ty_[j], ty_[j+st]);
                        tz_[j] = __hadd2(tz_[j], tz_[j+st]);
                        tw_[j] = __hadd2(tw_[j], tw_[j+st]);
                    }
                }
                float2 f;
                f = __half22float2(tx_[0]); acc[v*8+0] += f.x; acc[v*8+1] += f.y;
                f = __half22float2(ty_[0]); acc[v*8+2] += f.x; acc[v*8+3] += f.y;
                f = __half22float2(tz_[0]); acc[v*8+4] += f.x; acc[v*8+5] += f.y;
                f = __half22float2(tw_[0]); acc[v*8+6] += f.x; acc[v*8+7] += f.y;
            }
        }
    }
    for(; e < end; e++){
        int s0 = g_col[e];
        const uint4* r0 = in + s0*R;
#pragma unroll
        for(int v = 0; v < NV; v++){
            int idx = v*32 + lane;
            if(idx < R){
                uint4 q = r0[idx];
                float2 f;
                f = __half22float2(H2(q.x)); acc[v*8+0] += f.x; acc[v*8+1] += f.y;
                f = __half22float2(H2(q.y)); acc[v*8+2] += f.x; acc[v*8+3] += f.y;
                f = __half22float2(H2(q.z)); acc[v*8+4] += f.x; acc[v*8+5] += f.y;
                f = __half22float2(H2(q.w)); acc[v*8+6] += f.x; acc[v*8+7] += f.y;
            }
        }
    }
    float iv = g_invdeg[n];
#pragma unroll
    for(int k = 0; k < NV*8; k++) acc[k] *= iv;
}

// scatter gathered fp32 values into smem tile (t-major, 32 ch)
template<int T>
__device__ __forceinline__ void acc_to_tile(const float* acc, float* tile, int lane){
    constexpr int R  = T*4;
    constexpr int NV = (R + 31)/32;
#pragma unroll
    for(int v = 0; v < NV; v++){
        int idx = v*32 + lane;
        if(idx < R){
            int t = idx >> 2, c0 = (idx & 3) << 3;
            float4* tp = (float4*)(tile + t*32 + c0);
            tp[0] = make_float4(acc[v*8+0], acc[v*8+1], acc[v*8+2], acc[v*8+3]);
            tp[1] = make_float4(acc[v*8+4], acc[v*8+5], acc[v*8+6], acc[v*8+7]);
        }
    }
}

// load an fp16 row (own node, coalesced) into the fp32 smem tile
template<int T>
__device__ __forceinline__ void row_to_tile(const __half* __restrict__ row,
                                            float* tile, int lane){
    constexpr int R  = T*4;
    constexpr int NV = (R + 31)/32;
    const uint4* r4 = (const uint4*)row;
#pragma unroll
    for(int v = 0; v < NV; v++){
        int idx = v*32 + lane;
        if(idx < R){
            uint4 q = r4[idx];
            int t = idx >> 2, c0 = (idx & 3) << 3;
            float4* tp = (float4*)(tile + t*32 + c0);
            float2 fx = __half22float2(H2(q.x));
            float2 fy = __half22float2(H2(q.y));
            float2 fz = __half22float2(H2(q.z));
            float2 fw = __half22float2(H2(q.w));
            tp[0] = make_float4(fx.x, fx.y, fy.x, fy.y);
            tp[1] = make_float4(fz.x, fz.y, fw.x, fw.y);
        }
    }
}

// packed GEMM: a2[t] += pairs over K of tile[t][c] * W[c][lane]
template<int T>
__device__ __forceinline__ void gemm_acc2(const float* tile, const float* Ws,
                                          int lane, unsigned long long* a2){
#pragma unroll
    for(int c4 = 0; c4 < 8; c4++){
        unsigned long long W01 = packf2(Ws[(c4*4+0)*32+lane], Ws[(c4*4+1)*32+lane]);
        unsigned long long W23 = packf2(Ws[(c4*4+2)*32+lane], Ws[(c4*4+3)*32+lane]);
#pragma unroll
        for(int t = 0; t < T; t++){
            const ulonglong2* rp = (const ulonglong2*)(tile + t*32 + c4*4);
            ulonglong2 sv = *rp;
            a2[t] = ffma2(sv.x, W01, a2[t]);
            a2[t] = ffma2(sv.y, W23, a2[t]);
        }
    }
}

// store gathered acc as fp16 row
template<int T>
__device__ __forceinline__ void acc_store_h(const float* acc, __half* out, int n, int lane){
    constexpr int R  = T*4;
    constexpr int NV = (R + 31)/32;
    uint4* cp = (uint4*)out + n*R;
#pragma unroll
    for(int v = 0; v < NV; v++){
        int idx = v*32 + lane;
        if(idx < R){
            uint4 q;
            q.x = U2(__floats2half2_rn(acc[v*8+0], acc[v*8+1]));
            q.y = U2(__floats2half2_rn(acc[v*8+2], acc[v*8+3]));
            q.z = U2(__floats2half2_rn(acc[v*8+4], acc[v*8+5]));
            q.w = U2(__floats2half2_rn(acc[v*8+6], acc[v*8+7]));
            cp[idx] = q;
        }
    }
}

// ---------------- pure diffusion hop: out = A*in (fp16 -> fp16) ----------------
template<int T>
__global__ void __launch_bounds__(128) k_hop(
    const __half* __restrict__ in, __half* __restrict__ out)
{
    GRID_WAIT();
    constexpr int NV = (T*4 + 31)/32;
    int tid = threadIdx.x, lane = tid & 31, wid = tid >> 5;
    int n = blockIdx.x*PW + wid;
    float acc[NV*8];
    gather_row_h<T>((const uint4*)in, n, lane, acc);
    acc_store_h<T>(acc, out, n, lane);
}

// ---------------- propfin: p3 = A*p2 ; x = h@W0+p1@W1+p2@W2+p3@W3 + gcb + affine(xold); BN ----------------
template<int T, int TIN>
__global__ void __launch_bounds__(128) k_propfin(
    const __half* __restrict__ in,        // p2
    const __half* __restrict__ p1,
    const float* __restrict__ Wk4,        // 4x 32x32
    const float* __restrict__ xold, float* __restrict__ xnew,
    const float* __restrict__ gcb,
    const float* __restrict__ bng, const float* __restrict__ bnb, float invCnt)
{
    constexpr int NV = (T*4 + 31)/32;
    __shared__ float Ws[4096];
    __shared__ __align__(16) float smS[PW*12*32];
    __shared__ float rs[32*PW], rq[32*PW];
    __shared__ int isLast;
    int tid = threadIdx.x, lane = tid & 31, wid = tid >> 5;
    for(int j = tid; j < 4096; j += 128) Ws[j] = Wk4[j];
    __syncthreads();
    GRID_WAIT();

    int n = blockIdx.x*PW + wid;
    float acc[NV*8];
    gather_row_h<T>((const uint4*)in, n, lane, acc);   // p3

    unsigned long long a2[T];
#pragma unroll
    for(int t = 0; t < T; t++) a2[t] = 0ull;
    float* tile = smS + wid*(T*32);

    row_to_tile<T>(g_h + n*(T*32), tile, lane);  __syncwarp();
    gemm_acc2<T>(tile, Ws,        lane, a2);     __syncwarp();
    row_to_tile<T>(p1 + n*(T*32), tile, lane);   __syncwarp();
    gemm_acc2<T>(tile, Ws + 1024, lane, a2);     __syncwarp();
    row_to_tile<T>(in + n*(T*32), tile, lane);   __syncwarp();
    gemm_acc2<T>(tile, Ws + 2048, lane, a2);     __syncwarp();
    acc_to_tile<T>(acc, tile, lane);             __syncwarp();
    gemm_acc2<T>(tile, Ws + 3072, lane, a2);

    float scl = g_affine[lane], bia = g_affine[32+lane];
    float gb  = gcb[lane];
    const float* xo = xold + (n*TIN + (TIN-T))*32 + lane;
    float* xn = xnew + n*(T*32) + lane;
    float sum = 0.f, sq = 0.f;
#pragma unroll
    for(int t = 0; t < T; t++){
        float2 av = unpackf2(a2[t]);
        float v = (av.x + av.y) + gb + xo[t*32]*scl + bia;
        xn[t*32] = v;
        sum += v; sq += v*v;
    }
    rs[tid] = sum; rq[tid] = sq;
    __syncthreads();
    if(tid < 32){
        float ts = 0.f, tq = 0.f;
#pragma unroll
        for(int w = 0; w < PW; w++){ ts += rs[w*32+tid]; tq += rq[w*32+tid]; }
        int sh = (blockIdx.x & 31)*64;
        atomicAdd(&g_statsS[sh+tid],    (double)ts);
        atomicAdd(&g_statsS[sh+32+tid], (double)tq);
    }
    if(tid == 0){
        __threadfence();
        int d = atomicAdd(&g_done, 1);
        isLast = (d == (int)gridDim.x - 1) ? 1 : 0;
    }
    __syncthreads();
    if(isLast){
        __threadfence();
        if(tid < 32){
            double S = 0.0, Q = 0.0;
            for(int k = 0; k < 32; k++){ S += g_statsS[k*64+tid]; Q += g_statsS[k*64+32+tid]; }
            double mu  = S*(double)invCnt;
            double var = Q*(double)invCnt - mu*mu;
            if(var < 0.0) var = 0.0;
            float scale = bng[tid] * rsqrtf((float)var + 1e-5f);
            g_affine[tid]    = scale;
            g_affine[32+tid] = bnb[tid] - (float)mu*scale;
        }
        __syncthreads();
        for(int j = tid; j < 2048; j += 128) g_statsS[j] = 0.0;
        if(tid == 0) g_done = 0;
    }
}

// ---------------- head (f32x2 packed, transposed weights) ----------------
__global__ void __launch_bounds__(256) k_head(
    const float* __restrict__ sw_g, const float* __restrict__ sb_g,
    const float* __restrict__ b1, const float* __restrict__ b2,
    float* __restrict__ out)
{
    GRID_WAIT();
    extern __shared__ float sm[];
    float* hlsT    = sm;
    float* skipacc = sm + 5120;
    float* wbuf    = sm + 9216;
    float* y1s     = sm + 17440;
    int tid = threadIdx.x;
    int n0 = blockIdx.x*16;

    for(int j = tid; j < 8*16*32; j += 256){
        int c = j & 31, m = (j>>5) & 15, l = j>>9;
        hlsT[(l*32+c)*20 + m] = g_hl[l*(N_NODES*32) + (n0+m)*32 + c];
    }
    unsigned long long a2m[8];
    {
        float bs = 0.f;
        for(int l = 0; l < 8; l++) bs += sb_g[l*256+tid];
        unsigned long long bsp = packf2(bs, bs);
#pragma unroll
        for(int j = 0; j < 8; j++) a2m[j] = bsp;
    }
    for(int l = 0; l < 8; l++){
        __syncthreads();
        for(int j = tid; j < 8192; j += 256){
            int c = j & 31, O = j >> 5;
            wbuf[c*257+O] = sw_g[l*8192 + O*32 + c];
        }
        __syncthreads();
#pragma unroll 4
        for(int c = 0; c < 32; c++){
            float w = wbuf[c*257+tid];
            unsigned long long W = packf2(w, w);
            const ulonglong2* hp = (const ulonglong2*)(hlsT + (l*32+c)*20);
#pragma unroll
            for(int m4 = 0; m4 < 4; m4++){
                ulonglong2 h2 = hp[m4];
                a2m[m4*2+0] = ffma2(h2.x, W, a2m[m4*2+0]);
                a2m[m4*2+1] = ffma2(h2.y, W, a2m[m4*2+1]);
            }
        }
    }
    __syncthreads();
#pragma unroll
    for(int j = 0; j < 8; j++){
        float2 v = unpackf2(a2m[j]);
        skipacc[(2*j)*256+tid]   = fmaxf(v.x, 0.f);
        skipacc[(2*j+1)*256+tid] = fmaxf(v.y, 0.f);
    }
    __syncthreads();

    for(int oo = 0; oo < 2; oo++){
        int o = oo*256 + tid;
        unsigned long long acc2[16];
#pragma unroll
        for(int m = 0; m < 16; m++) acc2[m] = 0ull;
        const ulonglong2* sa = (const ulonglong2*)skipacc;
        for(int c4 = 0; c4 < 64; c4++){
            float wa = g_w1T[(c4*4+0)*512 + o];
            float wb = g_w1T[(c4*4+1)*512 + o];
            float wc = g_w1T[(c4*4+2)*512 + o];
            float wd = g_w1T[(c4*4+3)*512 + o];
            unsigned long long Wab = packf2(wa, wb);
            unsigned long long Wcd = packf2(wc, wd);
#pragma unroll
            for(int m = 0; m < 16; m++){
                ulonglong2 s = sa[m*64 + c4];
                acc2[m] = ffma2(s.x, Wab, acc2[m]);
                acc2[m] = ffma2(s.y, Wcd, acc2[m]);
            }
        }
        float bb = b1[o];
#pragma unroll
        for(int m = 0; m < 16; m++){
            float2 v = unpackf2(acc2[m]);
            y1s[m*512+o] = fmaxf(v.x + v.y + bb, 0.f);
        }
    }
    __syncthreads();

    for(int idx = tid; idx < 16*24; idx += 256){
        int m = idx/24, o = idx - 24*m;
        unsigned long long acc2 = 0ull;
        const ulonglong2* yp = (const ulonglong2*)(y1s + m*512);
        for(int c4 = 0; c4 < 128; c4++){
            float wa = g_w2T[(c4*4+0)*24 + o];
            float wb = g_w2T[(c4*4+1)*24 + o];
            float wc = g_w2T[(c4*4+2)*24 + o];
            float wd = g_w2T[(c4*4+3)*24 + o];
            ulonglong2 yy = yp[c4];
            acc2 = ffma2(yy.x, packf2(wa, wb), acc2);
            acc2 = ffma2(yy.y, packf2(wc, wd), acc2);
        }
        float2 v = unpackf2(acc2);
        out[(n0+m)*24 + o] = b2[o] + v.x + v.y;
    }
}

// ---------------- host ----------------
static inline size_t conv_smem(bool enter){
    return (size_t)(4096 + (enter ? 128 : 0) + NPB*32*20) * 4;
}

template<class K, class... A>
static inline void pdl(K k, int grid, int block, size_t smem, A... a){
    cudaLaunchConfig_t cfg;
    memset(&cfg, 0, sizeof(cfg));
    cfg.gridDim  = dim3((unsigned)grid, 1, 1);
    cfg.blockDim = dim3((unsigned)block, 1, 1);
    cfg.dynamicSmemBytes = smem;
    cfg.stream = 0;
    cudaLaunchAttribute at;
    at.id = cudaLaunchAttributeProgrammaticStreamSerialization;
    at.val.programmaticStreamSerializationAllowed = 1;
    cfg.attrs = &at;
    cfg.numAttrs = 1;
    cudaLaunchKernelEx(&cfg, k, a...);
}

extern "C" void kernel_launch(void* const* d_in, const int* in_sizes, int n_in,
                              void* d_out, int out_size)
{
    const float* inputs  = (const float*)d_in[0];
    const int*   esrc    = (const int*)  d_in[1];
    const int*   edst    = (const int*)  d_in[2];
    const float* enter_w = (const float*)d_in[3];
    const float* enter_b = (const float*)d_in[4];
    const float* filt_w  = (const float*)d_in[5];
    const float* filt_b  = (const float*)d_in[6];
    const float* gate_w  = (const float*)d_in[7];
    const float* gate_b  = (const float*)d_in[8];
    const float* gc_w    = (const float*)d_in[9];
    const float* gc_b    = (const float*)d_in[10];
    const float* skip_w  = (const float*)d_in[11];
    const float* skip_b  = (const float*)d_in[12];
    const float* bn_g    = (const float*)d_in[13];
    const float* bn_b    = (const float*)d_in[14];
    const float* out1_w  = (const float*)d_in[15];
    const float* out1_b  = (const float*)d_in[16];
    const float* out2_w  = (const float*)d_in[17];
    const float* out2_b  = (const float*)d_in[18];
    float* out = (float*)d_out;

    static int attr_set = 0;
    if(!attr_set){
        cudaFuncSetAttribute(k_head, cudaFuncAttributeMaxDynamicSharedMemorySize, 25632*4);
        attr_set = 1;
    }

    float *xA, *xB, *hl;
    __half *pA, *pB, *hh;
    float4 *wpk;
    cudaGetSymbolAddress((void**)&xA, g_xA);
    cudaGetSymbolAddress((void**)&xB, g_xB);
    cudaGetSymbolAddress((void**)&pA, g_pA);
    cudaGetSymbolAddress((void**)&pB, g_pB);
    cudaGetSymbolAddress((void**)&hh, g_h);
    cudaGetSymbolAddress((void**)&hl, g_hl);
    cudaGetSymbolAddress((void**)&wpk, g_wpk);

    const int GC = N_NODES/NPB;      // 2500
    const int GP = N_NODES/PW;       // 5000

    k_hist<<<(N_EDGES+255)/256, 256>>>(edst);
    k_trans<<<(512*256 + 24*512 + 8*1024 + 255)/256, 256>>>(out1_w, out2_w, filt_w, gate_w);
    pdl(k_scan, 1, 1024, 0);

    pdl(k_fillconv, 1250 + GC, 256, conv_smem(true),
        esrc, edst, inputs, enter_w, enter_b,
        (const float4*)(wpk + 0*1024), filt_b + 0*32, gate_b + 0*32,
        hl + 0*N_NODES*32, xA);
    pdl(k_hop<12>, GP, 128, (size_t)0, (const __half*)hh, pA);
    pdl(k_hop<12>, GP, 128, (size_t)0, (const __half*)pA, pB);
    pdl(k_propfin<12,13>, GP, 128, (size_t)0,
        (const __half*)pB, (const __half*)pA, gc_w + 0*4096,
        (const float*)xA, xB, gc_b + 0*32, bn_g + 0*32, bn_b + 0*32,
        1.f/((float)N_NODES*12.f));

#define LAYER(l, TIN, DD, XIN, XNEW)                                                         \
    {                                                                                        \
        const float t = (float)((TIN) - (DD));                                               \
        pdl(k_conv<TIN, DD, false, false>, GC, 256, conv_smem(false),                        \
            (const float*)XIN, (const float*)0, (const float*)0,                             \
            (const float4*)(wpk + (l)*1024), filt_b + (l)*32, gate_b + (l)*32,               \
            hl + (l)*N_NODES*32, (float*)0);                                                 \
        pdl(k_hop<(TIN)-(DD)>, GP, 128, (size_t)0, (const __half*)hh, pA);                   \
        pdl(k_hop<(TIN)-(DD)>, GP, 128, (size_t)0, (const __half*)pA, pB);                   \
        pdl(k_propfin<(TIN)-(DD), TIN>, GP, 128, (size_t)0,                                  \
            (const __half*)pB, (const __half*)pA, gc_w + (l)*4096,                           \
            (const float*)XIN, XNEW, gc_b + (l)*32, bn_g + (l)*32, bn_b + (l)*32,            \
            1.f/((float)N_NODES*t));                                                         \
    }

    LAYER(1, 12, 2, xB, xA)
    LAYER(2, 10, 1, xA, xB)
    LAYER(3,  9, 2, xB, xA)
    LAYER(4,  7, 1, xA, xB)
    LAYER(5,  6, 2, xB, xA)
    LAYER(6,  4, 1, xA, xB)
#undef LAYER

    // layer 7: conv + hl only
    pdl(k_conv<3,2,false,true>, GC, 256, conv_smem(false),
        (const float*)xB, (const float*)0, (const float*)0,
        (const float4*)(wpk + 7*1024), filt_b + 7*32, gate_b + 7*32,
        hl + 7*N_NODES*32, (float*)0);

    pdl(k_head, N_NODES/16, 256, (size_t)(25632*4),
        skip_w, skip_b, out1_b, out2_b, out);
}